// round 1
// baseline (speedup 1.0000x reference)
#include <cuda_runtime.h>

#define B_  16
#define C_  512
#define HW_ 4096

// ---------------- scratch (__device__ globals: allocation-free) ----------------
__device__ float g_xsum[B_ * C_];
__device__ float g_qv[B_ * C_];
__device__ float g_sk[B_ * C_];
__device__ float g_beff[B_ * C_];
__device__ float g_attn[(size_t)B_ * C_ * C_];   // 16.8 MB
__device__ float g_weff[(size_t)B_ * C_ * C_];   // 16.8 MB

// ---------------- warp reductions ----------------
__device__ __forceinline__ float warpSum(float v) {
#pragma unroll
    for (int o = 16; o > 0; o >>= 1) v += __shfl_xor_sync(0xffffffffu, v, o);
    return v;
}
__device__ __forceinline__ float warpMax(float v) {
#pragma unroll
    for (int o = 16; o > 0; o >>= 1) v = fmaxf(v, __shfl_xor_sync(0xffffffffu, v, o));
    return v;
}

// ---------------- kernel 1: xsum[b,c] = sum_n x[b,c,n] ----------------
__global__ void k_xsum(const float* __restrict__ x) {
    int row = blockIdx.x;  // b*C + c
    const float4* p = (const float4*)(x + (size_t)row * HW_);
    float s = 0.f;
#pragma unroll 4
    for (int i = threadIdx.x; i < HW_ / 4; i += 256) {
        float4 v = p[i];
        s += (v.x + v.y) + (v.z + v.w);
    }
    __shared__ float red[8];
    s = warpSum(s);
    if ((threadIdx.x & 31) == 0) red[threadIdx.x >> 5] = s;
    __syncthreads();
    if (threadIdx.x == 0) {
        float t = 0.f;
#pragma unroll
        for (int i = 0; i < 8; i++) t += red[i];
        g_xsum[row] = t;
    }
}

// ---------------- kernel 2: qv = wq@y + bq ; sk = wk@xsum + N*bk ----------------
__global__ void k_qvsk(const float* __restrict__ wq, const float* __restrict__ bq,
                       const float* __restrict__ wk, const float* __restrict__ bk,
                       const float* __restrict__ y) {
    int b = blockIdx.x;
    int o = threadIdx.x;  // 512 threads
    __shared__ float ys[C_], xs[C_];
    ys[o] = y[b * C_ + o];
    xs[o] = g_xsum[b * C_ + o];
    __syncthreads();
    const float4* wq4 = (const float4*)(wq + (size_t)o * C_);
    const float4* wk4 = (const float4*)(wk + (size_t)o * C_);
    float aq = 0.f, ak = 0.f;
#pragma unroll 4
    for (int c = 0; c < C_ / 4; c++) {
        float4 a = wq4[c], k4 = wk4[c];
        aq += a.x * ys[4 * c] + a.y * ys[4 * c + 1] + a.z * ys[4 * c + 2] + a.w * ys[4 * c + 3];
        ak += k4.x * xs[4 * c] + k4.y * xs[4 * c + 1] + k4.z * xs[4 * c + 2] + k4.w * xs[4 * c + 3];
    }
    g_qv[b * C_ + o] = aq + bq[o];
    g_sk[b * C_ + o] = ak + (float)HW_ * bk[o];
}

// ---------------- kernel 3: attn row softmax of qv[b,c]*sk[b,:] + beff ----------------
__global__ void k_softmax(const float* __restrict__ bv) {
    int b = blockIdx.y, c = blockIdx.x, d = threadIdx.x;  // 512 threads
    __shared__ float red[16];
    __shared__ float bc;
    float q = g_qv[b * C_ + c];
    float e = q * g_sk[b * C_ + d];

    // block max
    float m = warpMax(e);
    if ((d & 31) == 0) red[d >> 5] = m;
    __syncthreads();
    if (d < 32) {
        float v = (d < 16) ? red[d] : -3.4e38f;
        v = warpMax(v);
        if (d == 0) bc = v;
    }
    __syncthreads();
    m = bc;
    float ex = __expf(e - m);

    // block sum
    __syncthreads();
    float s = warpSum(ex);
    if ((d & 31) == 0) red[d >> 5] = s;
    __syncthreads();
    if (d < 32) {
        float v = (d < 16) ? red[d] : 0.f;
        v = warpSum(v);
        if (d == 0) bc = v;
    }
    __syncthreads();
    float a = ex / bc;
    g_attn[((size_t)(b * C_ + c)) * C_ + d] = a;

    // beff = attn-row . bv
    float pb = a * bv[d];
    __syncthreads();
    float s2 = warpSum(pb);
    if ((d & 31) == 0) red[d >> 5] = s2;
    __syncthreads();
    if (d < 32) {
        float v = (d < 16) ? red[d] : 0.f;
        v = warpSum(v);
        if (d == 0) g_beff[b * C_ + c] = v;
    }
}

// ---------------- kernel 4/5: tiled fp32 GEMM (128x128x16, 8x8 per thread) ----------------
// FINAL=false:  g_weff[b] = g_attn[b] (512x512) @ Bbase=wv (512x512)
// FINAL=true :  Out[b]    = gamma*(g_weff[b] @ Bbase=x[b] + beff) + x[b]
template <bool FINAL>
__global__ __launch_bounds__(256, 2) void k_gemm(const float* __restrict__ Bbase,
                                                 float* __restrict__ Obase,
                                                 const float* __restrict__ gamma) {
    constexpr int BM = 128, BN = 128, BK = 16;
    constexpr int LDN = FINAL ? HW_ : C_;

    int bb = blockIdx.z;
    int tile_n = blockIdx.x * BN;
    int tile_m = blockIdx.y * BM;

    const float* A = (FINAL ? g_weff : g_attn) + (size_t)bb * C_ * C_;
    const float* Bm = Bbase + (FINAL ? (size_t)bb * C_ * HW_ : 0);
    float* O = FINAL ? (Obase + (size_t)bb * C_ * HW_)
                     : (g_weff + (size_t)bb * C_ * C_);

    __shared__ float As[BK][BM];
    __shared__ float Bs[BK][BN];

    int t = threadIdx.x;
    int tx = t & 15, ty = t >> 4;

    float4 ra[2], rb[2];

    auto loadA = [&](int kt) {
#pragma unroll
        for (int u = 0; u < 2; u++) {
            int id = t + u * 256;
            int row = id >> 2, c4 = id & 3;
            ra[u] = *(const float4*)&A[(size_t)(tile_m + row) * C_ + kt * BK + c4 * 4];
        }
    };
    auto loadB = [&](int kt) {
#pragma unroll
        for (int u = 0; u < 2; u++) {
            int id = t + u * 256;
            int row = id >> 5, c4 = id & 31;
            rb[u] = *(const float4*)&Bm[(size_t)(kt * BK + row) * LDN + tile_n + c4 * 4];
        }
    };
    auto storeS = [&]() {
#pragma unroll
        for (int u = 0; u < 2; u++) {
            int id = t + u * 256;
            int arow = id >> 2, ac4 = id & 3;
            As[ac4 * 4 + 0][arow] = ra[u].x;
            As[ac4 * 4 + 1][arow] = ra[u].y;
            As[ac4 * 4 + 2][arow] = ra[u].z;
            As[ac4 * 4 + 3][arow] = ra[u].w;
            int brow = id >> 5, bc4 = id & 31;
            *(float4*)&Bs[brow][bc4 * 4] = rb[u];
        }
    };

    float acc[8][8];
#pragma unroll
    for (int i = 0; i < 8; i++)
#pragma unroll
        for (int j = 0; j < 8; j++) acc[i][j] = 0.f;

    constexpr int NK = C_ / BK;  // 32
    loadA(0);
    loadB(0);
#pragma unroll 1
    for (int kt = 0; kt < NK; kt++) {
        __syncthreads();
        storeS();
        __syncthreads();
        if (kt + 1 < NK) { loadA(kt + 1); loadB(kt + 1); }
#pragma unroll
        for (int k = 0; k < BK; k++) {
            float a[8], b[8];
            *(float4*)&a[0] = *(const float4*)&As[k][ty * 8];
            *(float4*)&a[4] = *(const float4*)&As[k][ty * 8 + 4];
            *(float4*)&b[0] = *(const float4*)&Bs[k][tx * 8];
            *(float4*)&b[4] = *(const float4*)&Bs[k][tx * 8 + 4];
#pragma unroll
            for (int i = 0; i < 8; i++)
#pragma unroll
                for (int j = 0; j < 8; j++) acc[i][j] = fmaf(a[i], b[j], acc[i][j]);
        }
    }

    float g = 0.f;
    if (FINAL) g = *gamma;
#pragma unroll
    for (int i = 0; i < 8; i++) {
        int r = tile_m + ty * 8 + i;
        float be = FINAL ? g_beff[bb * C_ + r] : 0.f;
#pragma unroll
        for (int j4 = 0; j4 < 2; j4++) {
            int ccol = tile_n + tx * 8 + j4 * 4;
            float4 v;
            if (FINAL) {
                float4 xv = *(const float4*)&Bm[(size_t)r * HW_ + ccol];
                v.x = g * (acc[i][j4 * 4 + 0] + be) + xv.x;
                v.y = g * (acc[i][j4 * 4 + 1] + be) + xv.y;
                v.z = g * (acc[i][j4 * 4 + 2] + be) + xv.z;
                v.w = g * (acc[i][j4 * 4 + 3] + be) + xv.w;
            } else {
                v.x = acc[i][j4 * 4 + 0];
                v.y = acc[i][j4 * 4 + 1];
                v.z = acc[i][j4 * 4 + 2];
                v.w = acc[i][j4 * 4 + 3];
            }
            *(float4*)&O[(size_t)r * LDN + ccol] = v;
        }
    }
}

// ---------------- launch ----------------
extern "C" void kernel_launch(void* const* d_in, const int* in_sizes, int n_in,
                              void* d_out, int out_size) {
    const float* x = (const float*)d_in[0];
    const float* y = (const float*)d_in[1];
    const float* wq = (const float*)d_in[2];
    const float* bq = (const float*)d_in[3];
    const float* wk = (const float*)d_in[4];
    const float* bk = (const float*)d_in[5];
    const float* wv = (const float*)d_in[6];
    const float* bv = (const float*)d_in[7];
    const float* gamma = (const float*)d_in[8];
    float* out = (float*)d_out;

    // 1) per-(b,c) spatial sum of x
    k_xsum<<<B_ * C_, 256>>>(x);
    // 2) qv[b,:] = wq@y[b] + bq ; sk[b,:] = wk@xsum[b] + N*bk
    k_qvsk<<<B_, C_>>>(wq, bq, wk, bk, y);
    // 3) attn[b,c,:] = softmax(qv[b,c]*sk[b,:]) ; beff = attn@bv
    k_softmax<<<dim3(C_, B_), C_>>>(bv);
    // 4) W_eff[b] = attn[b] @ wv    (512x512x512 per batch)
    k_gemm<false><<<dim3(C_ / 128, C_ / 128, B_), 256>>>(wv, nullptr, nullptr);
    // 5) out[b] = gamma*(W_eff[b] @ x[b] + beff) + x[b]
    k_gemm<true><<<dim3(HW_ / 128, C_ / 128, B_), 256>>>(x, out, gamma);
}

// round 4
// speedup vs baseline: 1.5086x; 1.5086x over previous
#include <cuda_runtime.h>
#include <cuda_bf16.h>
#include <cstdint>

#define B_  16
#define C_  512
#define HW_ 4096

// ---------------- scratch (__device__ globals: allocation-free) ----------------
__device__ float g_xsum[B_ * C_];
__device__ float g_qv[B_ * C_];
__device__ float g_sk[B_ * C_];
__device__ float g_beff[B_ * C_];
__device__ float g_attn[(size_t)B_ * C_ * C_];                 // 16.8 MB fp32
__device__ __nv_bfloat16 g_whi[(size_t)B_ * C_ * C_];          // 8.4 MB
__device__ __nv_bfloat16 g_wlo[(size_t)B_ * C_ * C_];          // 8.4 MB
__device__ __nv_bfloat16 g_xthi[(size_t)B_ * HW_ * C_];        // 67 MB  [b][n][k]
__device__ __nv_bfloat16 g_xtlo[(size_t)B_ * HW_ * C_];        // 67 MB  [b][n][k]

// ---------------- small helpers ----------------
__device__ __forceinline__ uint32_t smem_u32(const void* p) {
    uint32_t a;
    asm("{ .reg .u64 t; cvta.to.shared.u64 t, %1; cvt.u32.u64 %0, t; }" : "=r"(a) : "l"(p));
    return a;
}
__device__ __forceinline__ void cp_async16(uint32_t dst, const void* src) {
    asm volatile("cp.async.cg.shared.global [%0], [%1], 16;" :: "r"(dst), "l"(src) : "memory");
}
__device__ __forceinline__ void cp_commit() {
    asm volatile("cp.async.commit_group;" ::: "memory");
}
template <int N>
__device__ __forceinline__ void cp_wait() {
    asm volatile("cp.async.wait_group %0;" :: "n"(N) : "memory");
}
// SW64 swizzle for 64-byte rows (4 x 16B chunks rotated by (row>>1)&3)
__device__ __forceinline__ uint32_t sw64(uint32_t off) { return off ^ ((off >> 3) & 0x30); }

__device__ __forceinline__ void ldsm_x4(uint32_t* r, uint32_t addr) {
    asm volatile("ldmatrix.sync.aligned.m8n8.x4.shared.b16 {%0,%1,%2,%3}, [%4];"
                 : "=r"(r[0]), "=r"(r[1]), "=r"(r[2]), "=r"(r[3]) : "r"(addr));
}
__device__ __forceinline__ void mma16816(float* c, const uint32_t* a, const uint32_t* b) {
    asm volatile(
        "mma.sync.aligned.m16n8k16.row.col.f32.bf16.bf16.f32 "
        "{%0,%1,%2,%3}, {%4,%5,%6,%7}, {%8,%9}, {%0,%1,%2,%3};"
        : "+f"(c[0]), "+f"(c[1]), "+f"(c[2]), "+f"(c[3])
        : "r"(a[0]), "r"(a[1]), "r"(a[2]), "r"(a[3]), "r"(b[0]), "r"(b[1]));
}

// ---------------- warp reductions ----------------
__device__ __forceinline__ float warpSum(float v) {
#pragma unroll
    for (int o = 16; o > 0; o >>= 1) v += __shfl_xor_sync(0xffffffffu, v, o);
    return v;
}
__device__ __forceinline__ float warpMax(float v) {
#pragma unroll
    for (int o = 16; o > 0; o >>= 1) v = fmaxf(v, __shfl_xor_sync(0xffffffffu, v, o));
    return v;
}

// ---------------- kernel 1: xsum[b,c] = sum_n x[b,c,n] ----------------
__global__ void k_xsum(const float* __restrict__ x) {
    int row = blockIdx.x;
    const float4* p = (const float4*)(x + (size_t)row * HW_);
    float s = 0.f;
#pragma unroll 4
    for (int i = threadIdx.x; i < HW_ / 4; i += 256) {
        float4 v = p[i];
        s += (v.x + v.y) + (v.z + v.w);
    }
    __shared__ float red[8];
    s = warpSum(s);
    if ((threadIdx.x & 31) == 0) red[threadIdx.x >> 5] = s;
    __syncthreads();
    if (threadIdx.x == 0) {
        float t = 0.f;
#pragma unroll
        for (int i = 0; i < 8; i++) t += red[i];
        g_xsum[row] = t;
    }
}

// ---------------- kernel 2: qv = wq@y + bq ; sk = wk@xsum + N*bk ----------------
__global__ void k_qvsk(const float* __restrict__ wq, const float* __restrict__ bq,
                       const float* __restrict__ wk, const float* __restrict__ bk,
                       const float* __restrict__ y) {
    int b = blockIdx.x;
    int o = threadIdx.x;
    __shared__ float ys[C_], xs[C_];
    ys[o] = y[b * C_ + o];
    xs[o] = g_xsum[b * C_ + o];
    __syncthreads();
    const float4* wq4 = (const float4*)(wq + (size_t)o * C_);
    const float4* wk4 = (const float4*)(wk + (size_t)o * C_);
    float aq = 0.f, ak = 0.f;
#pragma unroll 4
    for (int c = 0; c < C_ / 4; c++) {
        float4 a = wq4[c], k4 = wk4[c];
        aq += a.x * ys[4 * c] + a.y * ys[4 * c + 1] + a.z * ys[4 * c + 2] + a.w * ys[4 * c + 3];
        ak += k4.x * xs[4 * c] + k4.y * xs[4 * c + 1] + k4.z * xs[4 * c + 2] + k4.w * xs[4 * c + 3];
    }
    g_qv[b * C_ + o] = aq + bq[o];
    g_sk[b * C_ + o] = ak + (float)HW_ * bk[o];
}

// ---------------- kernel 3: attn softmax + beff ----------------
__global__ void k_softmax(const float* __restrict__ bv) {
    int b = blockIdx.y, c = blockIdx.x, d = threadIdx.x;
    __shared__ float red[16];
    __shared__ float bc;
    float q = g_qv[b * C_ + c];
    float e = q * g_sk[b * C_ + d];

    float m = warpMax(e);
    if ((d & 31) == 0) red[d >> 5] = m;
    __syncthreads();
    if (d < 32) {
        float v = (d < 16) ? red[d] : -3.4e38f;
        v = warpMax(v);
        if (d == 0) bc = v;
    }
    __syncthreads();
    m = bc;
    float ex = __expf(e - m);
    __syncthreads();
    float s = warpSum(ex);
    if ((d & 31) == 0) red[d >> 5] = s;
    __syncthreads();
    if (d < 32) {
        float v = (d < 16) ? red[d] : 0.f;
        v = warpSum(v);
        if (d == 0) bc = v;
    }
    __syncthreads();
    float a = ex / bc;
    g_attn[((size_t)(b * C_ + c)) * C_ + d] = a;

    float pb = a * bv[d];
    __syncthreads();
    float s2 = warpSum(pb);
    if ((d & 31) == 0) red[d >> 5] = s2;
    __syncthreads();
    if (d < 32) {
        float v = (d < 16) ? red[d] : 0.f;
        v = warpSum(v);
        if (d == 0) g_beff[b * C_ + c] = v;
    }
}

// ---------------- kernel 4: convert+transpose x -> xt_hi/xt_lo [b][n][k] ----------------
__global__ void k_cvt_x(const float* __restrict__ x) {
    __shared__ float tile[64][65];
    int b = blockIdx.z;
    int n0 = blockIdx.x * 64;
    int k0 = blockIdx.y * 64;
    int t = threadIdx.x;
    int tr = t >> 4, tc = t & 15;

    const float* src = x + ((size_t)b * C_ + k0) * HW_ + n0;
#pragma unroll
    for (int i = 0; i < 4; i++) {
        int r = tr + i * 16;  // local k
        float4 v = *(const float4*)(src + (size_t)r * HW_ + tc * 4);
        tile[r][tc * 4 + 0] = v.x;
        tile[r][tc * 4 + 1] = v.y;
        tile[r][tc * 4 + 2] = v.z;
        tile[r][tc * 4 + 3] = v.w;
    }
    __syncthreads();
#pragma unroll
    for (int i = 0; i < 4; i++) {
        int n = tr + i * 16;  // local n
        size_t base = ((size_t)(b * HW_ + n0 + n)) * C_ + k0 + tc * 4;
        float v[4];
#pragma unroll
        for (int j = 0; j < 4; j++) v[j] = tile[tc * 4 + j][n];
        __nv_bfloat16 h[4], l[4];
#pragma unroll
        for (int j = 0; j < 4; j++) {
            h[j] = __float2bfloat16(v[j]);
            l[j] = __float2bfloat16(v[j] - __bfloat162float(h[j]));
        }
        *(__nv_bfloat162*)&g_xthi[base]     = __nv_bfloat162(h[0], h[1]);
        *(__nv_bfloat162*)&g_xthi[base + 2] = __nv_bfloat162(h[2], h[3]);
        *(__nv_bfloat162*)&g_xtlo[base]     = __nv_bfloat162(l[0], l[1]);
        *(__nv_bfloat162*)&g_xtlo[base + 2] = __nv_bfloat162(l[2], l[3]);
    }
}

// ---------------- kernel 5: W_eff = attn @ wv (fp32 SIMT), emit bf16 hi/lo ----------------
__global__ __launch_bounds__(256, 2) void k_wgemm(const float* __restrict__ wv) {
    constexpr int BM = 128, BN = 128, BK = 16;
    int bb = blockIdx.z;
    int tile_n = blockIdx.x * BN;
    int tile_m = blockIdx.y * BM;

    const float* A = g_attn + (size_t)bb * C_ * C_;
    const float* Bm = wv;

    __shared__ float As[BK][BM];
    __shared__ float Bs[BK][BN];

    int t = threadIdx.x;
    int tx = t & 15, ty = t >> 4;
    float4 ra[2], rb[2];

    auto loadA = [&](int kt) {
#pragma unroll
        for (int u = 0; u < 2; u++) {
            int id = t + u * 256;
            int row = id >> 2, c4 = id & 3;
            ra[u] = *(const float4*)&A[(size_t)(tile_m + row) * C_ + kt * BK + c4 * 4];
        }
    };
    auto loadB = [&](int kt) {
#pragma unroll
        for (int u = 0; u < 2; u++) {
            int id = t + u * 256;
            int row = id >> 5, c4 = id & 31;
            rb[u] = *(const float4*)&Bm[(size_t)(kt * BK + row) * C_ + tile_n + c4 * 4];
        }
    };
    auto storeS = [&]() {
#pragma unroll
        for (int u = 0; u < 2; u++) {
            int id = t + u * 256;
            int arow = id >> 2, ac4 = id & 3;
            As[ac4 * 4 + 0][arow] = ra[u].x;
            As[ac4 * 4 + 1][arow] = ra[u].y;
            As[ac4 * 4 + 2][arow] = ra[u].z;
            As[ac4 * 4 + 3][arow] = ra[u].w;
            int brow = id >> 5, bc4 = id & 31;
            *(float4*)&Bs[brow][bc4 * 4] = rb[u];
        }
    };

    float acc[8][8];
#pragma unroll
    for (int i = 0; i < 8; i++)
#pragma unroll
        for (int j = 0; j < 8; j++) acc[i][j] = 0.f;

    constexpr int NK = C_ / BK;
    loadA(0);
    loadB(0);
#pragma unroll 1
    for (int kt = 0; kt < NK; kt++) {
        __syncthreads();
        storeS();
        __syncthreads();
        if (kt + 1 < NK) { loadA(kt + 1); loadB(kt + 1); }
#pragma unroll
        for (int k = 0; k < BK; k++) {
            float a[8], bq[8];
            *(float4*)&a[0] = *(const float4*)&As[k][ty * 8];
            *(float4*)&a[4] = *(const float4*)&As[k][ty * 8 + 4];
            *(float4*)&bq[0] = *(const float4*)&Bs[k][tx * 8];
            *(float4*)&bq[4] = *(const float4*)&Bs[k][tx * 8 + 4];
#pragma unroll
            for (int i = 0; i < 8; i++)
#pragma unroll
                for (int j = 0; j < 8; j++) acc[i][j] = fmaf(a[i], bq[j], acc[i][j]);
        }
    }

#pragma unroll
    for (int i = 0; i < 8; i++) {
        int r = tile_m + ty * 8 + i;
#pragma unroll
        for (int j4 = 0; j4 < 2; j4++) {
            int ccol = tile_n + tx * 8 + j4 * 4;
            size_t idx = ((size_t)(bb * C_ + r)) * C_ + ccol;
            __nv_bfloat16 h[4], l[4];
#pragma unroll
            for (int j = 0; j < 4; j++) {
                float v = acc[i][j4 * 4 + j];
                h[j] = __float2bfloat16(v);
                l[j] = __float2bfloat16(v - __bfloat162float(h[j]));
            }
            *(__nv_bfloat162*)&g_whi[idx]     = __nv_bfloat162(h[0], h[1]);
            *(__nv_bfloat162*)&g_whi[idx + 2] = __nv_bfloat162(h[2], h[3]);
            *(__nv_bfloat162*)&g_wlo[idx]     = __nv_bfloat162(l[0], l[1]);
            *(__nv_bfloat162*)&g_wlo[idx + 2] = __nv_bfloat162(l[2], l[3]);
        }
    }
}

// ---------------- kernel 6: mma.sync bf16 main GEMM + fused epilogue ----------------
// out[b, tm..tm+128, tn..tn+128] = gamma*(D + beff) + x,
// D = (Whi+Wlo) @ (XThi+XTlo)^T using hh + hl + lh passes, fp32 accum.
#define MM_BM 128
#define MM_BN 128
#define MM_BK 32
#define MM_NKT (C_ / MM_BK)       // 16
#define MM_STAGE 32768            // 4 arrays x 8KB
#define MM_ARR 8192
#define MM_SMEM (2 * MM_STAGE)    // 64 KB

__global__ __launch_bounds__(256, 1) void k_mma_final(
    const float* __restrict__ x, float* __restrict__ out,
    const float* __restrict__ gamma) {
    extern __shared__ char smem[];
    uint32_t sb = smem_u32(smem);
    int t = threadIdx.x;
    int wid = t >> 5, lane = t & 31;
    int wm = wid & 3, wn = wid >> 2;
    int b = blockIdx.z;
    int tm = blockIdx.y * MM_BM;
    int tn = blockIdx.x * MM_BN;

    const __nv_bfloat16* srcAh = g_whi + ((size_t)b * C_ + tm) * C_;
    const __nv_bfloat16* srcAl = g_wlo + ((size_t)b * C_ + tm) * C_;
    const __nv_bfloat16* srcBh = g_xthi + ((size_t)b * HW_ + tn) * C_;
    const __nv_bfloat16* srcBl = g_xtlo + ((size_t)b * HW_ + tn) * C_;

    int lrow = t >> 2;          // 0..63; with 2 chunks covers 128 rows
    int lc = t & 3;             // 16B chunk within 64B row

    auto load_stage = [&](int kt, int buf) {
        uint32_t base = sb + buf * MM_STAGE;
#pragma unroll
        for (int i = 0; i < 2; i++) {
            int row = lrow + i * 64;
            uint32_t soff = sw64((uint32_t)(row * 64 + lc * 16));
            size_t goff = (size_t)row * C_ + kt * MM_BK + lc * 8;
            cp_async16(base + soff, srcAh + goff);
            cp_async16(base + MM_ARR + soff, srcAl + goff);
            cp_async16(base + 2 * MM_ARR + soff, srcBh + goff);
            cp_async16(base + 3 * MM_ARR + soff, srcBl + goff);
        }
        cp_commit();
    };

    float acc[2][8][4];
#pragma unroll
    for (int mt = 0; mt < 2; mt++)
#pragma unroll
        for (int nt = 0; nt < 8; nt++)
#pragma unroll
            for (int q = 0; q < 4; q++) acc[mt][nt][q] = 0.f;

    load_stage(0, 0);
    load_stage(1, 1);
    cp_wait<1>();
    __syncthreads();

#pragma unroll 1
    for (int kt = 0; kt < MM_NKT; kt++) {
        int buf = kt & 1;
        uint32_t Ah = sb + buf * MM_STAGE;
        uint32_t Al = Ah + MM_ARR;
        uint32_t Bh = Ah + 2 * MM_ARR;
        uint32_t Bl = Ah + 3 * MM_ARR;

#pragma unroll
        for (int s = 0; s < 2; s++) {
            // ---- A fragments: rows wm*32 + mt*16 + (lane&15), chunk 2s + (lane>>4)
            uint32_t ah[2][4], al[2][4];
#pragma unroll
            for (int mt = 0; mt < 2; mt++) {
                int row = wm * 32 + mt * 16 + (lane & 15);
                int ch = 2 * s + (lane >> 4);
                uint32_t off = sw64((uint32_t)(row * 64 + ch * 16));
                ldsm_x4(ah[mt], Ah + off);
                ldsm_x4(al[mt], Al + off);
            }
            // ---- B fragments (NON-trans: smem is [n][k], k contiguous, which is
            //      exactly the mma.col B fragment layout): rows wn*64 + ng*16 +
            //      (lane&7) + ((lane&16)>>1), chunk 2s + ((lane>>3)&1)
            uint32_t bh[8][2], bl[8][2];
#pragma unroll
            for (int ng = 0; ng < 4; ng++) {
                int row = wn * 64 + ng * 16 + (lane & 7) + ((lane & 16) >> 1);
                int ch = 2 * s + ((lane >> 3) & 1);
                uint32_t off = sw64((uint32_t)(row * 64 + ch * 16));
                uint32_t r4[4];
                ldsm_x4(r4, Bh + off);
                bh[ng * 2 + 0][0] = r4[0]; bh[ng * 2 + 0][1] = r4[1];
                bh[ng * 2 + 1][0] = r4[2]; bh[ng * 2 + 1][1] = r4[3];
                ldsm_x4(r4, Bl + off);
                bl[ng * 2 + 0][0] = r4[0]; bl[ng * 2 + 0][1] = r4[1];
                bl[ng * 2 + 1][0] = r4[2]; bl[ng * 2 + 1][1] = r4[3];
            }
            // ---- MMAs: hh + hl + lh
#pragma unroll
            for (int mt = 0; mt < 2; mt++)
#pragma unroll
                for (int nt = 0; nt < 8; nt++) {
                    mma16816(acc[mt][nt], ah[mt], bh[nt]);
                    mma16816(acc[mt][nt], ah[mt], bl[nt]);
                    mma16816(acc[mt][nt], al[mt], bh[nt]);
                }
        }

        if (kt + 1 < MM_NKT) {
            __syncthreads();
            if (kt + 2 < MM_NKT) {
                load_stage(kt + 2, buf);
                cp_wait<1>();
            } else {
                cp_wait<0>();
            }
            __syncthreads();
        }
    }

    // ---- epilogue: out = gamma*(acc + beff) + x
    float g = *gamma;
    int r0 = tm + wm * 32 + (lane >> 2);
    int c0 = tn + wn * 64 + (lane & 3) * 2;
#pragma unroll
    for (int mt = 0; mt < 2; mt++) {
#pragma unroll
        for (int half = 0; half < 2; half++) {
            int row = r0 + mt * 16 + half * 8;
            float be = g_beff[b * C_ + row];
            const float2* xr = (const float2*)(x + ((size_t)b * C_ + row) * HW_ + c0);
            float2* orow = (float2*)(out + ((size_t)b * C_ + row) * HW_ + c0);
#pragma unroll
            for (int nt = 0; nt < 8; nt++) {
                float2 xv = xr[nt * 4];
                float va = acc[mt][nt][half * 2 + 0];
                float vb = acc[mt][nt][half * 2 + 1];
                float2 o;
                o.x = g * (va + be) + xv.x;
                o.y = g * (vb + be) + xv.y;
                orow[nt * 4] = o;
            }
        }
    }
}

// ---------------- launch ----------------
extern "C" void kernel_launch(void* const* d_in, const int* in_sizes, int n_in,
                              void* d_out, int out_size) {
    const float* x = (const float*)d_in[0];
    const float* y = (const float*)d_in[1];
    const float* wq = (const float*)d_in[2];
    const float* bq = (const float*)d_in[3];
    const float* wk = (const float*)d_in[4];
    const float* bk = (const float*)d_in[5];
    const float* wv = (const float*)d_in[6];
    const float* bv = (const float*)d_in[7];
    const float* gamma = (const float*)d_in[8];
    float* out = (float*)d_out;

    static bool configured = false;
    if (!configured) {
        cudaFuncSetAttribute(k_mma_final, cudaFuncAttributeMaxDynamicSharedMemorySize, MM_SMEM);
        configured = true;
    }

    // independent: convert+transpose x to bf16 hi/lo [b][n][k]
    k_cvt_x<<<dim3(HW_ / 64, C_ / 64, B_), 256>>>(x);
    // chain: xsum -> qv/sk -> softmax(attn,beff) -> W_eff(hi/lo)
    k_xsum<<<B_ * C_, 256>>>(x);
    k_qvsk<<<B_, C_>>>(wq, bq, wk, bk, y);
    k_softmax<<<dim3(C_, B_), C_>>>(bv);
    k_wgemm<<<dim3(C_ / 128, C_ / 128, B_), 256>>>(wv);
    // main mma.sync GEMM + fused residual epilogue
    k_mma_final<<<dim3(HW_ / MM_BN, C_ / MM_BM, B_), 256, MM_SMEM>>>(x, out, gamma);
}

// round 5
// speedup vs baseline: 2.7001x; 1.7898x over previous
#include <cuda_runtime.h>
#include <cuda_fp16.h>
#include <cstdint>

#define B_  16
#define C_  512
#define HW_ 4096

// ---------------- scratch (__device__ globals: allocation-free) ----------------
__device__ float g_xsum[B_ * C_];
__device__ float g_qv[B_ * C_];
__device__ float g_sk[B_ * C_];
__device__ float g_beff[B_ * C_];
__device__ __half g_ahi[(size_t)B_ * C_ * C_];   // attn hi  [b][c][d]
__device__ __half g_alo[(size_t)B_ * C_ * C_];   // attn lo
__device__ __half g_wvhi[C_ * C_];               // wv^T hi  [c][o]
__device__ __half g_wvlo[C_ * C_];               // wv^T lo
__device__ __half g_whi[(size_t)B_ * C_ * C_];   // W_eff hi [b][m][k]
__device__ __half g_wlo[(size_t)B_ * C_ * C_];   // W_eff lo
__device__ __half g_xt[(size_t)B_ * HW_ * C_];   // x^T fp16 [b][n][k]  (67 MB)

// ---------------- helpers ----------------
__device__ __forceinline__ uint32_t smem_u32(const void* p) {
    uint32_t a;
    asm("{ .reg .u64 t; cvta.to.shared.u64 t, %1; cvt.u32.u64 %0, t; }" : "=r"(a) : "l"(p));
    return a;
}
__device__ __forceinline__ void cp_async16(uint32_t dst, const void* src) {
    asm volatile("cp.async.cg.shared.global [%0], [%1], 16;" :: "r"(dst), "l"(src) : "memory");
}
__device__ __forceinline__ void cp_commit() {
    asm volatile("cp.async.commit_group;" ::: "memory");
}
template <int N>
__device__ __forceinline__ void cp_wait() {
    asm volatile("cp.async.wait_group %0;" :: "n"(N) : "memory");
}
__device__ __forceinline__ uint32_t sw64(uint32_t off) { return off ^ ((off >> 3) & 0x30); }

__device__ __forceinline__ void ldsm_x4(uint32_t* r, uint32_t addr) {
    asm volatile("ldmatrix.sync.aligned.m8n8.x4.shared.b16 {%0,%1,%2,%3}, [%4];"
                 : "=r"(r[0]), "=r"(r[1]), "=r"(r[2]), "=r"(r[3]) : "r"(addr));
}
__device__ __forceinline__ void mma16816(float* c, const uint32_t* a, const uint32_t* b) {
    asm volatile(
        "mma.sync.aligned.m16n8k16.row.col.f32.f16.f16.f32 "
        "{%0,%1,%2,%3}, {%4,%5,%6,%7}, {%8,%9}, {%0,%1,%2,%3};"
        : "+f"(c[0]), "+f"(c[1]), "+f"(c[2]), "+f"(c[3])
        : "r"(a[0]), "r"(a[1]), "r"(a[2]), "r"(a[3]), "r"(b[0]), "r"(b[1]));
}

__device__ __forceinline__ float warpSum(float v) {
#pragma unroll
    for (int o = 16; o > 0; o >>= 1) v += __shfl_xor_sync(0xffffffffu, v, o);
    return v;
}
__device__ __forceinline__ float warpMax(float v) {
#pragma unroll
    for (int o = 16; o > 0; o >>= 1) v = fmaxf(v, __shfl_xor_sync(0xffffffffu, v, o));
    return v;
}

// ---------------- kernel 0: zero xsum ----------------
__global__ void k_zero() {
    int t = blockIdx.x * 256 + threadIdx.x;
    if (t < B_ * C_) g_xsum[t] = 0.f;
}

// ---------------- kernel 1: transpose+convert x -> g_xt fp16 [b][n][k], fused xsum ----------------
__global__ void k_cvtx(const float* __restrict__ x) {
    __shared__ float tile[64][65];
    int b = blockIdx.z;
    int n0 = blockIdx.x * 64;
    int k0 = blockIdx.y * 64;
    int t = threadIdx.x;
    int tr = t >> 4, tc = t & 15;

    const float* src = x + ((size_t)b * C_ + k0) * HW_ + n0;
    float psum[4];
#pragma unroll
    for (int i = 0; i < 4; i++) {
        int r = tr + i * 16;  // local k
        float4 v = *(const float4*)(src + (size_t)r * HW_ + tc * 4);
        tile[r][tc * 4 + 0] = v.x;
        tile[r][tc * 4 + 1] = v.y;
        tile[r][tc * 4 + 2] = v.z;
        tile[r][tc * 4 + 3] = v.w;
        psum[i] = (v.x + v.y) + (v.z + v.w);
    }
    // xsum: reduce psum[i] across the 16 threads (tc) sharing each row, then atomicAdd
#pragma unroll
    for (int i = 0; i < 4; i++) {
        float s = psum[i];
#pragma unroll
        for (int o = 8; o > 0; o >>= 1) s += __shfl_xor_sync(0xffffffffu, s, o);
        if (tc == 0) atomicAdd(&g_xsum[b * C_ + k0 + tr + i * 16], s);
    }
    __syncthreads();
#pragma unroll
    for (int i = 0; i < 4; i++) {
        int n = tr + i * 16;  // local n
        size_t base = ((size_t)(b * HW_ + n0 + n)) * C_ + k0 + tc * 4;
        float v0 = tile[tc * 4 + 0][n];
        float v1 = tile[tc * 4 + 1][n];
        float v2 = tile[tc * 4 + 2][n];
        float v3 = tile[tc * 4 + 3][n];
        *(__half2*)&g_xt[base]     = __floats2half2_rn(v0, v1);
        *(__half2*)&g_xt[base + 2] = __floats2half2_rn(v2, v3);
    }
}

// ---------------- kernel 2: wv^T -> fp16 hi/lo [c][o] ----------------
__global__ void k_wvt(const float* __restrict__ wv) {
    __shared__ float tile[64][65];
    int o0 = blockIdx.y * 64;   // source rows (o)
    int c0 = blockIdx.x * 64;   // source cols (c)
    int t = threadIdx.x;
    int tr = t >> 4, tc = t & 15;

    const float* src = wv + (size_t)(o0)*C_ + c0;
#pragma unroll
    for (int i = 0; i < 4; i++) {
        int r = tr + i * 16;  // local o
        float4 v = *(const float4*)(src + (size_t)r * C_ + tc * 4);
        tile[r][tc * 4 + 0] = v.x;
        tile[r][tc * 4 + 1] = v.y;
        tile[r][tc * 4 + 2] = v.z;
        tile[r][tc * 4 + 3] = v.w;
    }
    __syncthreads();
#pragma unroll
    for (int i = 0; i < 4; i++) {
        int c = tr + i * 16;  // local c
        size_t base = (size_t)(c0 + c) * C_ + o0 + tc * 4;
#pragma unroll
        for (int j = 0; j < 4; j += 2) {
            float va = tile[tc * 4 + j][c];
            float vb = tile[tc * 4 + j + 1][c];
            __half2 h = __floats2half2_rn(va, vb);
            __half2 l = __floats2half2_rn(va - __low2float(h), vb - __high2float(h));
            *(__half2*)&g_wvhi[base + j] = h;
            *(__half2*)&g_wvlo[base + j] = l;
        }
    }
}

// ---------------- kernel 3: qv = wq@y + bq ; sk = wk@xsum + N*bk ----------------
__global__ void k_qvsk(const float* __restrict__ wq, const float* __restrict__ bq,
                       const float* __restrict__ wk, const float* __restrict__ bk,
                       const float* __restrict__ y) {
    int b = blockIdx.x;
    int o = threadIdx.x;
    __shared__ float ys[C_], xs[C_];
    ys[o] = y[b * C_ + o];
    xs[o] = g_xsum[b * C_ + o];
    __syncthreads();
    const float4* wq4 = (const float4*)(wq + (size_t)o * C_);
    const float4* wk4 = (const float4*)(wk + (size_t)o * C_);
    float aq = 0.f, ak = 0.f;
#pragma unroll 4
    for (int c = 0; c < C_ / 4; c++) {
        float4 a = wq4[c], k4 = wk4[c];
        aq += a.x * ys[4 * c] + a.y * ys[4 * c + 1] + a.z * ys[4 * c + 2] + a.w * ys[4 * c + 3];
        ak += k4.x * xs[4 * c] + k4.y * xs[4 * c + 1] + k4.z * xs[4 * c + 2] + k4.w * xs[4 * c + 3];
    }
    g_qv[b * C_ + o] = aq + bq[o];
    g_sk[b * C_ + o] = ak + (float)HW_ * bk[o];
}

// ---------------- kernel 4: softmax -> attn fp16 hi/lo + beff (1 warp/row) ----------------
__global__ void k_softmax(const float* __restrict__ bv) {
    int b = blockIdx.y;
    int w = threadIdx.x >> 5, lane = threadIdx.x & 31;
    int c = blockIdx.x * 8 + w;
    __shared__ float sks[C_], bvs[C_];
    for (int i = threadIdx.x; i < C_; i += 256) {
        sks[i] = g_sk[b * C_ + i];
        bvs[i] = bv[i];
    }
    __syncthreads();

    float q = g_qv[b * C_ + c];
    float e[16];
    float m = -3.4e38f;
#pragma unroll
    for (int i = 0; i < 16; i++) {
        e[i] = q * sks[lane + 32 * i];
        m = fmaxf(m, e[i]);
    }
    m = warpMax(m);
    float s = 0.f;
#pragma unroll
    for (int i = 0; i < 16; i++) {
        e[i] = __expf(e[i] - m);
        s += e[i];
    }
    s = warpSum(s);
    float inv = 1.f / s;
    float bacc = 0.f;
    size_t base = ((size_t)(b * C_ + c)) * C_;
#pragma unroll
    for (int i = 0; i < 16; i++) {
        float a = e[i] * inv;
        __half h = __float2half(a);
        g_ahi[base + lane + 32 * i] = h;
        g_alo[base + lane + 32 * i] = __float2half(a - __half2float(h));
        bacc += a * bvs[lane + 32 * i];
    }
    bacc = warpSum(bacc);
    if (lane == 0) g_beff[b * C_ + c] = bacc;
}

// ---------------- kernel 5: W_eff = attn @ wv^T  (fp16 3-pass tensor) ----------------
// A = attn hi/lo [m][k], B = wvt hi/lo [n][k]; D -> W_eff fp16 hi/lo.
#define WG_ARR 8192
#define WG_STAGE (4 * WG_ARR)       // 32 KB
#define WG_SMEM (2 * WG_STAGE)      // 64 KB

__global__ __launch_bounds__(256, 1) void k_wgemm() {
    extern __shared__ char smem[];
    uint32_t sb = smem_u32(smem);
    int t = threadIdx.x;
    int wid = t >> 5, lane = t & 31;
    int wm = wid & 3, wn = wid >> 2;
    int b = blockIdx.z;
    int tm = blockIdx.y * 128;
    int tn = blockIdx.x * 128;

    const __half* srcAh = g_ahi + ((size_t)b * C_ + tm) * C_;
    const __half* srcAl = g_alo + ((size_t)b * C_ + tm) * C_;
    const __half* srcBh = g_wvhi + (size_t)tn * C_;
    const __half* srcBl = g_wvlo + (size_t)tn * C_;

    int lrow = t >> 2;
    int lc = t & 3;

    auto load_stage = [&](int kt, int buf) {
        uint32_t base = sb + buf * WG_STAGE;
#pragma unroll
        for (int i = 0; i < 2; i++) {
            int row = lrow + i * 64;
            uint32_t soff = sw64((uint32_t)(row * 64 + lc * 16));
            size_t goff = (size_t)row * C_ + kt * 32 + lc * 8;
            cp_async16(base + soff, srcAh + goff);
            cp_async16(base + WG_ARR + soff, srcAl + goff);
            cp_async16(base + 2 * WG_ARR + soff, srcBh + goff);
            cp_async16(base + 3 * WG_ARR + soff, srcBl + goff);
        }
        cp_commit();
    };

    float acc[2][8][4];
#pragma unroll
    for (int mt = 0; mt < 2; mt++)
#pragma unroll
        for (int nt = 0; nt < 8; nt++)
#pragma unroll
            for (int q = 0; q < 4; q++) acc[mt][nt][q] = 0.f;

    load_stage(0, 0);
    load_stage(1, 1);
    cp_wait<1>();
    __syncthreads();

#pragma unroll 1
    for (int kt = 0; kt < 16; kt++) {
        int buf = kt & 1;
        uint32_t Ah = sb + buf * WG_STAGE;
        uint32_t Al = Ah + WG_ARR;
        uint32_t Bh = Ah + 2 * WG_ARR;
        uint32_t Bl = Ah + 3 * WG_ARR;

#pragma unroll
        for (int s = 0; s < 2; s++) {
            uint32_t ah[2][4], al[2][4];
#pragma unroll
            for (int mt = 0; mt < 2; mt++) {
                int row = wm * 32 + mt * 16 + (lane & 15);
                int ch = 2 * s + (lane >> 4);
                uint32_t off = sw64((uint32_t)(row * 64 + ch * 16));
                ldsm_x4(ah[mt], Ah + off);
                ldsm_x4(al[mt], Al + off);
            }
            uint32_t bh[8][2], bl[8][2];
#pragma unroll
            for (int ng = 0; ng < 4; ng++) {
                int row = wn * 64 + ng * 16 + (lane & 7) + ((lane & 16) >> 1);
                int ch = 2 * s + ((lane >> 3) & 1);
                uint32_t off = sw64((uint32_t)(row * 64 + ch * 16));
                uint32_t r4[4];
                ldsm_x4(r4, Bh + off);
                bh[ng * 2 + 0][0] = r4[0]; bh[ng * 2 + 0][1] = r4[1];
                bh[ng * 2 + 1][0] = r4[2]; bh[ng * 2 + 1][1] = r4[3];
                ldsm_x4(r4, Bl + off);
                bl[ng * 2 + 0][0] = r4[0]; bl[ng * 2 + 0][1] = r4[1];
                bl[ng * 2 + 1][0] = r4[2]; bl[ng * 2 + 1][1] = r4[3];
            }
#pragma unroll
            for (int mt = 0; mt < 2; mt++)
#pragma unroll
                for (int nt = 0; nt < 8; nt++) {
                    mma16816(acc[mt][nt], ah[mt], bh[nt]);
                    mma16816(acc[mt][nt], ah[mt], bl[nt]);
                    mma16816(acc[mt][nt], al[mt], bh[nt]);
                }
        }

        if (kt + 1 < 16) {
            __syncthreads();
            if (kt + 2 < 16) {
                load_stage(kt + 2, buf);
                cp_wait<1>();
            } else {
                cp_wait<0>();
            }
            __syncthreads();
        }
    }

    // epilogue: W_eff -> fp16 hi/lo
    int r0 = tm + wm * 32 + (lane >> 2);
    int c0 = tn + wn * 64 + (lane & 3) * 2;
#pragma unroll
    for (int mt = 0; mt < 2; mt++) {
#pragma unroll
        for (int half = 0; half < 2; half++) {
            int row = r0 + mt * 16 + half * 8;
            size_t rbase = ((size_t)(b * C_ + row)) * C_;
#pragma unroll
            for (int nt = 0; nt < 8; nt++) {
                int col = c0 + nt * 8;
                float va = acc[mt][nt][half * 2 + 0];
                float vb = acc[mt][nt][half * 2 + 1];
                __half2 h = __floats2half2_rn(va, vb);
                __half2 l = __floats2half2_rn(va - __low2float(h), vb - __high2float(h));
                *(__half2*)&g_whi[rbase + col] = h;
                *(__half2*)&g_wlo[rbase + col] = l;
            }
        }
    }
}

// ---------------- kernel 6: main GEMM, fp16 2-pass: D = (Wh+Wl) @ xt^T ----------------
#define MM_ARR 8192
#define MM_STAGE (3 * MM_ARR)       // 24 KB (Ah, Al, Bh)
#define MM_SMEM (2 * MM_STAGE)      // 48 KB

__global__ __launch_bounds__(256, 2) void k_main(
    const float* __restrict__ x, float* __restrict__ out,
    const float* __restrict__ gamma) {
    extern __shared__ char smem[];
    uint32_t sb = smem_u32(smem);
    int t = threadIdx.x;
    int wid = t >> 5, lane = t & 31;
    int wm = wid & 3, wn = wid >> 2;
    int b = blockIdx.z;
    int tm = blockIdx.y * 128;
    int tn = blockIdx.x * 128;

    const __half* srcAh = g_whi + ((size_t)b * C_ + tm) * C_;
    const __half* srcAl = g_wlo + ((size_t)b * C_ + tm) * C_;
    const __half* srcBh = g_xt + ((size_t)b * HW_ + tn) * C_;

    int lrow = t >> 2;
    int lc = t & 3;

    auto load_stage = [&](int kt, int buf) {
        uint32_t base = sb + buf * MM_STAGE;
#pragma unroll
        for (int i = 0; i < 2; i++) {
            int row = lrow + i * 64;
            uint32_t soff = sw64((uint32_t)(row * 64 + lc * 16));
            size_t goff = (size_t)row * C_ + kt * 32 + lc * 8;
            cp_async16(base + soff, srcAh + goff);
            cp_async16(base + MM_ARR + soff, srcAl + goff);
            cp_async16(base + 2 * MM_ARR + soff, srcBh + goff);
        }
        cp_commit();
    };

    float acc[2][8][4];
#pragma unroll
    for (int mt = 0; mt < 2; mt++)
#pragma unroll
        for (int nt = 0; nt < 8; nt++)
#pragma unroll
            for (int q = 0; q < 4; q++) acc[mt][nt][q] = 0.f;

    load_stage(0, 0);
    load_stage(1, 1);
    cp_wait<1>();
    __syncthreads();

#pragma unroll 1
    for (int kt = 0; kt < 16; kt++) {
        int buf = kt & 1;
        uint32_t Ah = sb + buf * MM_STAGE;
        uint32_t Al = Ah + MM_ARR;
        uint32_t Bh = Ah + 2 * MM_ARR;

#pragma unroll
        for (int s = 0; s < 2; s++) {
            uint32_t ah[2][4], al[2][4];
#pragma unroll
            for (int mt = 0; mt < 2; mt++) {
                int row = wm * 32 + mt * 16 + (lane & 15);
                int ch = 2 * s + (lane >> 4);
                uint32_t off = sw64((uint32_t)(row * 64 + ch * 16));
                ldsm_x4(ah[mt], Ah + off);
                ldsm_x4(al[mt], Al + off);
            }
            uint32_t bh[8][2];
#pragma unroll
            for (int ng = 0; ng < 4; ng++) {
                int row = wn * 64 + ng * 16 + (lane & 7) + ((lane & 16) >> 1);
                int ch = 2 * s + ((lane >> 3) & 1);
                uint32_t off = sw64((uint32_t)(row * 64 + ch * 16));
                uint32_t r4[4];
                ldsm_x4(r4, Bh + off);
                bh[ng * 2 + 0][0] = r4[0]; bh[ng * 2 + 0][1] = r4[1];
                bh[ng * 2 + 1][0] = r4[2]; bh[ng * 2 + 1][1] = r4[3];
            }
#pragma unroll
            for (int mt = 0; mt < 2; mt++)
#pragma unroll
                for (int nt = 0; nt < 8; nt++) {
                    mma16816(acc[mt][nt], ah[mt], bh[nt]);
                    mma16816(acc[mt][nt], al[mt], bh[nt]);
                }
        }

        if (kt + 1 < 16) {
            __syncthreads();
            if (kt + 2 < 16) {
                load_stage(kt + 2, buf);
                cp_wait<1>();
            } else {
                cp_wait<0>();
            }
            __syncthreads();
        }
    }

    // epilogue: out = gamma*(acc + beff) + x
    float g = *gamma;
    int r0 = tm + wm * 32 + (lane >> 2);
    int c0 = tn + wn * 64 + (lane & 3) * 2;
#pragma unroll
    for (int mt = 0; mt < 2; mt++) {
#pragma unroll
        for (int half = 0; half < 2; half++) {
            int row = r0 + mt * 16 + half * 8;
            float be = g_beff[b * C_ + row];
            const float2* xr = (const float2*)(x + ((size_t)b * C_ + row) * HW_ + c0);
            float2* orow = (float2*)(out + ((size_t)b * C_ + row) * HW_ + c0);
#pragma unroll
            for (int nt = 0; nt < 8; nt++) {
                float2 xv = xr[nt * 4];
                float2 o;
                o.x = g * (acc[mt][nt][half * 2 + 0] + be) + xv.x;
                o.y = g * (acc[mt][nt][half * 2 + 1] + be) + xv.y;
                orow[nt * 4] = o;
            }
        }
    }
}

// ---------------- launch ----------------
extern "C" void kernel_launch(void* const* d_in, const int* in_sizes, int n_in,
                              void* d_out, int out_size) {
    const float* x = (const float*)d_in[0];
    const float* y = (const float*)d_in[1];
    const float* wq = (const float*)d_in[2];
    const float* bq = (const float*)d_in[3];
    const float* wk = (const float*)d_in[4];
    const float* bk = (const float*)d_in[5];
    const float* wv = (const float*)d_in[6];
    const float* bv = (const float*)d_in[7];
    const float* gamma = (const float*)d_in[8];
    float* out = (float*)d_out;

    static bool configured = false;
    if (!configured) {
        cudaFuncSetAttribute(k_wgemm, cudaFuncAttributeMaxDynamicSharedMemorySize, WG_SMEM);
        cudaFuncSetAttribute(k_main, cudaFuncAttributeMaxDynamicSharedMemorySize, MM_SMEM);
        configured = true;
    }

    k_zero<<<(B_ * C_ + 255) / 256, 256>>>();
    k_cvtx<<<dim3(HW_ / 64, C_ / 64, B_), 256>>>(x);        // xt fp16 + xsum (atomics)
    k_wvt<<<dim3(C_ / 64, C_ / 64), 256>>>(wv);             // wv^T hi/lo
    k_qvsk<<<B_, C_>>>(wq, bq, wk, bk, y);
    k_softmax<<<dim3(C_ / 8, B_), 256>>>(bv);               // attn hi/lo + beff
    k_wgemm<<<dim3(C_ / 128, C_ / 128, B_), 256, WG_SMEM>>>();
    k_main<<<dim3(HW_ / 128, C_ / 128, B_), 256, MM_SMEM>>>(x, out, gamma);
}

// round 6
// speedup vs baseline: 3.2180x; 1.1918x over previous
#include <cuda_runtime.h>
#include <cuda_fp16.h>
#include <cstdint>

#define B_  16
#define C_  512
#define HW_ 4096

// ---------------- scratch (__device__ globals: allocation-free) ----------------
__device__ float g_xsum[B_ * C_];
__device__ float g_qv[B_ * C_];
__device__ float g_sk[B_ * C_];
__device__ float g_beff[B_ * C_];
__device__ __half g_ahi[(size_t)B_ * C_ * C_];   // attn hi  [b][c][d]
__device__ __half g_alo[(size_t)B_ * C_ * C_];   // attn lo
__device__ __half g_wvhi[C_ * C_];               // wv^T hi  [c][o]
__device__ __half g_wvlo[C_ * C_];               // wv^T lo
__device__ __half g_whi[(size_t)B_ * C_ * C_];   // W_eff hi [b][m][k]
__device__ __half g_wlo[(size_t)B_ * C_ * C_];   // W_eff lo
__device__ __half g_xt[(size_t)B_ * HW_ * C_];   // x^T fp16 [b][n][k]  (67 MB)

// ---------------- helpers ----------------
__device__ __forceinline__ uint32_t smem_u32(const void* p) {
    uint32_t a;
    asm("{ .reg .u64 t; cvta.to.shared.u64 t, %1; cvt.u32.u64 %0, t; }" : "=r"(a) : "l"(p));
    return a;
}
__device__ __forceinline__ void cp_async16(uint32_t dst, const void* src) {
    asm volatile("cp.async.cg.shared.global [%0], [%1], 16;" :: "r"(dst), "l"(src) : "memory");
}
__device__ __forceinline__ void cp_commit() {
    asm volatile("cp.async.commit_group;" ::: "memory");
}
template <int N>
__device__ __forceinline__ void cp_wait() {
    asm volatile("cp.async.wait_group %0;" :: "n"(N) : "memory");
}
__device__ __forceinline__ uint32_t sw64(uint32_t off) { return off ^ ((off >> 3) & 0x30); }

__device__ __forceinline__ void ldsm_x4(uint32_t* r, uint32_t addr) {
    asm volatile("ldmatrix.sync.aligned.m8n8.x4.shared.b16 {%0,%1,%2,%3}, [%4];"
                 : "=r"(r[0]), "=r"(r[1]), "=r"(r[2]), "=r"(r[3]) : "r"(addr));
}
__device__ __forceinline__ void mma16816(float* c, const uint32_t* a, const uint32_t* b) {
    asm volatile(
        "mma.sync.aligned.m16n8k16.row.col.f32.f16.f16.f32 "
        "{%0,%1,%2,%3}, {%4,%5,%6,%7}, {%8,%9}, {%0,%1,%2,%3};"
        : "+f"(c[0]), "+f"(c[1]), "+f"(c[2]), "+f"(c[3])
        : "r"(a[0]), "r"(a[1]), "r"(a[2]), "r"(a[3]), "r"(b[0]), "r"(b[1]));
}

__device__ __forceinline__ float warpSum(float v) {
#pragma unroll
    for (int o = 16; o > 0; o >>= 1) v += __shfl_xor_sync(0xffffffffu, v, o);
    return v;
}
__device__ __forceinline__ float warpMax(float v) {
#pragma unroll
    for (int o = 16; o > 0; o >>= 1) v = fmaxf(v, __shfl_xor_sync(0xffffffffu, v, o));
    return v;
}

// ---------------- kernel 0: zero xsum ----------------
__global__ void k_zero() {
    int t = blockIdx.x * 256 + threadIdx.x;
    if (t < B_ * C_) g_xsum[t] = 0.f;
}

// ---------------- kernel 1: transpose+convert x -> g_xt fp16 [b][n][k], fused xsum ----------------
__global__ void k_cvtx(const float* __restrict__ x) {
    __shared__ float tile[64][65];
    int b = blockIdx.z;
    int n0 = blockIdx.x * 64;
    int k0 = blockIdx.y * 64;
    int t = threadIdx.x;
    int tr = t >> 4, tc = t & 15;

    const float* src = x + ((size_t)b * C_ + k0) * HW_ + n0;
    float psum[4];
#pragma unroll
    for (int i = 0; i < 4; i++) {
        int r = tr + i * 16;  // local k
        float4 v = *(const float4*)(src + (size_t)r * HW_ + tc * 4);
        tile[r][tc * 4 + 0] = v.x;
        tile[r][tc * 4 + 1] = v.y;
        tile[r][tc * 4 + 2] = v.z;
        tile[r][tc * 4 + 3] = v.w;
        psum[i] = (v.x + v.y) + (v.z + v.w);
    }
#pragma unroll
    for (int i = 0; i < 4; i++) {
        float s = psum[i];
#pragma unroll
        for (int o = 8; o > 0; o >>= 1) s += __shfl_xor_sync(0xffffffffu, s, o);
        if (tc == 0) atomicAdd(&g_xsum[b * C_ + k0 + tr + i * 16], s);
    }
    __syncthreads();
#pragma unroll
    for (int i = 0; i < 4; i++) {
        int n = tr + i * 16;  // local n
        size_t base = ((size_t)(b * HW_ + n0 + n)) * C_ + k0 + tc * 4;
        float v0 = tile[tc * 4 + 0][n];
        float v1 = tile[tc * 4 + 1][n];
        float v2 = tile[tc * 4 + 2][n];
        float v3 = tile[tc * 4 + 3][n];
        *(__half2*)&g_xt[base]     = __floats2half2_rn(v0, v1);
        *(__half2*)&g_xt[base + 2] = __floats2half2_rn(v2, v3);
    }
}

// ---------------- kernel 2: wv^T -> fp16 hi/lo [c][o] ----------------
__global__ void k_wvt(const float* __restrict__ wv) {
    __shared__ float tile[64][65];
    int o0 = blockIdx.y * 64;
    int c0 = blockIdx.x * 64;
    int t = threadIdx.x;
    int tr = t >> 4, tc = t & 15;

    const float* src = wv + (size_t)(o0)*C_ + c0;
#pragma unroll
    for (int i = 0; i < 4; i++) {
        int r = tr + i * 16;
        float4 v = *(const float4*)(src + (size_t)r * C_ + tc * 4);
        tile[r][tc * 4 + 0] = v.x;
        tile[r][tc * 4 + 1] = v.y;
        tile[r][tc * 4 + 2] = v.z;
        tile[r][tc * 4 + 3] = v.w;
    }
    __syncthreads();
#pragma unroll
    for (int i = 0; i < 4; i++) {
        int c = tr + i * 16;
        size_t base = (size_t)(c0 + c) * C_ + o0 + tc * 4;
#pragma unroll
        for (int j = 0; j < 4; j += 2) {
            float va = tile[tc * 4 + j][c];
            float vb = tile[tc * 4 + j + 1][c];
            __half2 h = __floats2half2_rn(va, vb);
            __half2 l = __floats2half2_rn(va - __low2float(h), vb - __high2float(h));
            *(__half2*)&g_wvhi[base + j] = h;
            *(__half2*)&g_wvlo[base + j] = l;
        }
    }
}

// ---------------- kernel 3: qv/sk, parallel: grid (C/64, B), 4 threads per output ----------------
__global__ void k_qvsk(const float* __restrict__ wq, const float* __restrict__ bq,
                       const float* __restrict__ wk, const float* __restrict__ bk,
                       const float* __restrict__ y) {
    int b = blockIdx.y;
    int o0 = blockIdx.x * 64;
    __shared__ float ys[C_], xs[C_];
    for (int i = threadIdx.x; i < C_; i += 256) {
        ys[i] = y[b * C_ + i];
        xs[i] = g_xsum[b * C_ + i];
    }
    __syncthreads();

    int ot = threadIdx.x >> 2;       // 0..63
    int ks = threadIdx.x & 3;        // k-slice
    int o = o0 + ot;
    const float4* wq4 = (const float4*)(wq + (size_t)o * C_ + ks * 128);
    const float4* wk4 = (const float4*)(wk + (size_t)o * C_ + ks * 128);
    const float* yss = ys + ks * 128;
    const float* xss = xs + ks * 128;
    float aq = 0.f, ak = 0.f;
#pragma unroll 8
    for (int c = 0; c < 32; c++) {
        float4 a = wq4[c], k4 = wk4[c];
        aq += a.x * yss[4 * c] + a.y * yss[4 * c + 1] + a.z * yss[4 * c + 2] + a.w * yss[4 * c + 3];
        ak += k4.x * xss[4 * c] + k4.y * xss[4 * c + 1] + k4.z * xss[4 * c + 2] + k4.w * xss[4 * c + 3];
    }
    aq += __shfl_xor_sync(0xffffffffu, aq, 1);
    aq += __shfl_xor_sync(0xffffffffu, aq, 2);
    ak += __shfl_xor_sync(0xffffffffu, ak, 1);
    ak += __shfl_xor_sync(0xffffffffu, ak, 2);
    if (ks == 0) {
        g_qv[b * C_ + o] = aq + bq[o];
        g_sk[b * C_ + o] = ak + (float)HW_ * bk[o];
    }
}

// ---------------- kernel 4: softmax -> attn fp16 hi/lo + beff (1 warp/row) ----------------
__global__ void k_softmax(const float* __restrict__ bv) {
    int b = blockIdx.y;
    int w = threadIdx.x >> 5, lane = threadIdx.x & 31;
    int c = blockIdx.x * 8 + w;
    __shared__ float sks[C_], bvs[C_];
    for (int i = threadIdx.x; i < C_; i += 256) {
        sks[i] = g_sk[b * C_ + i];
        bvs[i] = bv[i];
    }
    __syncthreads();

    float q = g_qv[b * C_ + c];
    float e[16];
    float m = -3.4e38f;
#pragma unroll
    for (int i = 0; i < 16; i++) {
        e[i] = q * sks[lane + 32 * i];
        m = fmaxf(m, e[i]);
    }
    m = warpMax(m);
    float s = 0.f;
#pragma unroll
    for (int i = 0; i < 16; i++) {
        e[i] = __expf(e[i] - m);
        s += e[i];
    }
    s = warpSum(s);
    float inv = 1.f / s;
    float bacc = 0.f;
    size_t base = ((size_t)(b * C_ + c)) * C_;
#pragma unroll
    for (int i = 0; i < 16; i++) {
        float a = e[i] * inv;
        __half h = __float2half(a);
        g_ahi[base + lane + 32 * i] = h;
        g_alo[base + lane + 32 * i] = __float2half(a - __half2float(h));
        bacc += a * bvs[lane + 32 * i];
    }
    bacc = warpSum(bacc);
    if (lane == 0) g_beff[b * C_ + c] = bacc;
}

// ---------------- kernel 5: W_eff = attn @ wv^T (fp16 3-pass, 3-stage pipeline) ----------------
#define WG_ARR 8192
#define WG_STAGE (4 * WG_ARR)       // 32 KB
#define WG_SMEM (3 * WG_STAGE)      // 96 KB

__global__ __launch_bounds__(256, 1) void k_wgemm() {
    extern __shared__ char smem[];
    uint32_t sb = smem_u32(smem);
    int t = threadIdx.x;
    int wid = t >> 5, lane = t & 31;
    int wm = wid & 3, wn = wid >> 2;
    int b = blockIdx.z;
    int tm = blockIdx.y * 128;
    int tn = blockIdx.x * 128;

    const __half* srcAh = g_ahi + ((size_t)b * C_ + tm) * C_;
    const __half* srcAl = g_alo + ((size_t)b * C_ + tm) * C_;
    const __half* srcBh = g_wvhi + (size_t)tn * C_;
    const __half* srcBl = g_wvlo + (size_t)tn * C_;

    int lrow = t >> 2;
    int lc = t & 3;

    auto load_stage = [&](int kt, int st) {
        uint32_t base = sb + st * WG_STAGE;
#pragma unroll
        for (int i = 0; i < 2; i++) {
            int row = lrow + i * 64;
            uint32_t soff = sw64((uint32_t)(row * 64 + lc * 16));
            size_t goff = (size_t)row * C_ + kt * 32 + lc * 8;
            cp_async16(base + soff, srcAh + goff);
            cp_async16(base + WG_ARR + soff, srcAl + goff);
            cp_async16(base + 2 * WG_ARR + soff, srcBh + goff);
            cp_async16(base + 3 * WG_ARR + soff, srcBl + goff);
        }
        cp_commit();
    };

    float acc[2][8][4];
#pragma unroll
    for (int mt = 0; mt < 2; mt++)
#pragma unroll
        for (int nt = 0; nt < 8; nt++)
#pragma unroll
            for (int q = 0; q < 4; q++) acc[mt][nt][q] = 0.f;

    load_stage(0, 0);
    load_stage(1, 1);

#pragma unroll 1
    for (int kt = 0; kt < 16; kt++) {
        if (kt < 14) cp_wait<1>();
        else cp_wait<0>();
        __syncthreads();
        if (kt + 2 < 16) load_stage(kt + 2, (kt + 2) % 3);

        uint32_t Ah = sb + (kt % 3) * WG_STAGE;
        uint32_t Al = Ah + WG_ARR;
        uint32_t Bh = Ah + 2 * WG_ARR;
        uint32_t Bl = Ah + 3 * WG_ARR;

#pragma unroll
        for (int s = 0; s < 2; s++) {
            uint32_t ah[2][4], al[2][4];
#pragma unroll
            for (int mt = 0; mt < 2; mt++) {
                int row = wm * 32 + mt * 16 + (lane & 15);
                int ch = 2 * s + (lane >> 4);
                uint32_t off = sw64((uint32_t)(row * 64 + ch * 16));
                ldsm_x4(ah[mt], Ah + off);
                ldsm_x4(al[mt], Al + off);
            }
            uint32_t bh[8][2], bl[8][2];
#pragma unroll
            for (int ng = 0; ng < 4; ng++) {
                int row = wn * 64 + ng * 16 + (lane & 7) + ((lane & 16) >> 1);
                int ch = 2 * s + ((lane >> 3) & 1);
                uint32_t off = sw64((uint32_t)(row * 64 + ch * 16));
                uint32_t r4[4];
                ldsm_x4(r4, Bh + off);
                bh[ng * 2 + 0][0] = r4[0]; bh[ng * 2 + 0][1] = r4[1];
                bh[ng * 2 + 1][0] = r4[2]; bh[ng * 2 + 1][1] = r4[3];
                ldsm_x4(r4, Bl + off);
                bl[ng * 2 + 0][0] = r4[0]; bl[ng * 2 + 0][1] = r4[1];
                bl[ng * 2 + 1][0] = r4[2]; bl[ng * 2 + 1][1] = r4[3];
            }
#pragma unroll
            for (int mt = 0; mt < 2; mt++)
#pragma unroll
                for (int nt = 0; nt < 8; nt++) {
                    mma16816(acc[mt][nt], ah[mt], bh[nt]);
                    mma16816(acc[mt][nt], ah[mt], bl[nt]);
                    mma16816(acc[mt][nt], al[mt], bh[nt]);
                }
        }
    }

    int r0 = tm + wm * 32 + (lane >> 2);
    int c0 = tn + wn * 64 + (lane & 3) * 2;
#pragma unroll
    for (int mt = 0; mt < 2; mt++) {
#pragma unroll
        for (int half = 0; half < 2; half++) {
            int row = r0 + mt * 16 + half * 8;
            size_t rbase = ((size_t)(b * C_ + row)) * C_;
#pragma unroll
            for (int nt = 0; nt < 8; nt++) {
                int col = c0 + nt * 8;
                float va = acc[mt][nt][half * 2 + 0];
                float vb = acc[mt][nt][half * 2 + 1];
                __half2 h = __floats2half2_rn(va, vb);
                __half2 l = __floats2half2_rn(va - __low2float(h), vb - __high2float(h));
                *(__half2*)&g_whi[rbase + col] = h;
                *(__half2*)&g_wlo[rbase + col] = l;
            }
        }
    }
}

// ---------------- kernel 6: main GEMM, fp16 2-pass, 3-stage pipeline ----------------
#define MM_ARR 8192
#define MM_STAGE (3 * MM_ARR)       // 24 KB (Ah, Al, Bh)
#define MM_SMEM (3 * MM_STAGE)      // 72 KB

__global__ __launch_bounds__(256, 2) void k_main(
    const float* __restrict__ x, float* __restrict__ out,
    const float* __restrict__ gamma) {
    extern __shared__ char smem[];
    uint32_t sb = smem_u32(smem);
    int t = threadIdx.x;
    int wid = t >> 5, lane = t & 31;
    int wm = wid & 3, wn = wid >> 2;
    int b = blockIdx.z;
    int tm = blockIdx.y * 128;
    int tn = blockIdx.x * 128;

    const __half* srcAh = g_whi + ((size_t)b * C_ + tm) * C_;
    const __half* srcAl = g_wlo + ((size_t)b * C_ + tm) * C_;
    const __half* srcBh = g_xt + ((size_t)b * HW_ + tn) * C_;

    int lrow = t >> 2;
    int lc = t & 3;

    auto load_stage = [&](int kt, int st) {
        uint32_t base = sb + st * MM_STAGE;
#pragma unroll
        for (int i = 0; i < 2; i++) {
            int row = lrow + i * 64;
            uint32_t soff = sw64((uint32_t)(row * 64 + lc * 16));
            size_t goff = (size_t)row * C_ + kt * 32 + lc * 8;
            cp_async16(base + soff, srcAh + goff);
            cp_async16(base + MM_ARR + soff, srcAl + goff);
            cp_async16(base + 2 * MM_ARR + soff, srcBh + goff);
        }
        cp_commit();
    };

    float acc[2][8][4];
#pragma unroll
    for (int mt = 0; mt < 2; mt++)
#pragma unroll
        for (int nt = 0; nt < 8; nt++)
#pragma unroll
            for (int q = 0; q < 4; q++) acc[mt][nt][q] = 0.f;

    load_stage(0, 0);
    load_stage(1, 1);

#pragma unroll 1
    for (int kt = 0; kt < 16; kt++) {
        if (kt < 14) cp_wait<1>();
        else cp_wait<0>();
        __syncthreads();
        if (kt + 2 < 16) load_stage(kt + 2, (kt + 2) % 3);

        uint32_t Ah = sb + (kt % 3) * MM_STAGE;
        uint32_t Al = Ah + MM_ARR;
        uint32_t Bh = Ah + 2 * MM_ARR;

#pragma unroll
        for (int s = 0; s < 2; s++) {
            uint32_t ah[2][4], al[2][4];
#pragma unroll
            for (int mt = 0; mt < 2; mt++) {
                int row = wm * 32 + mt * 16 + (lane & 15);
                int ch = 2 * s + (lane >> 4);
                uint32_t off = sw64((uint32_t)(row * 64 + ch * 16));
                ldsm_x4(ah[mt], Ah + off);
                ldsm_x4(al[mt], Al + off);
            }
            uint32_t bh[8][2];
#pragma unroll
            for (int ng = 0; ng < 4; ng++) {
                int row = wn * 64 + ng * 16 + (lane & 7) + ((lane & 16) >> 1);
                int ch = 2 * s + ((lane >> 3) & 1);
                uint32_t off = sw64((uint32_t)(row * 64 + ch * 16));
                uint32_t r4[4];
                ldsm_x4(r4, Bh + off);
                bh[ng * 2 + 0][0] = r4[0]; bh[ng * 2 + 0][1] = r4[1];
                bh[ng * 2 + 1][0] = r4[2]; bh[ng * 2 + 1][1] = r4[3];
            }
#pragma unroll
            for (int mt = 0; mt < 2; mt++)
#pragma unroll
                for (int nt = 0; nt < 8; nt++) {
                    mma16816(acc[mt][nt], ah[mt], bh[nt]);
                    mma16816(acc[mt][nt], al[mt], bh[nt]);
                }
        }
    }

    // epilogue: out = gamma*(acc + beff) + x
    float g = *gamma;
    int r0 = tm + wm * 32 + (lane >> 2);
    int c0 = tn + wn * 64 + (lane & 3) * 2;
#pragma unroll
    for (int mt = 0; mt < 2; mt++) {
#pragma unroll
        for (int half = 0; half < 2; half++) {
            int row = r0 + mt * 16 + half * 8;
            float be = g_beff[b * C_ + row];
            const float2* xr = (const float2*)(x + ((size_t)b * C_ + row) * HW_ + c0);
            float2* orow = (float2*)(out + ((size_t)b * C_ + row) * HW_ + c0);
#pragma unroll
            for (int nt = 0; nt < 8; nt++) {
                float2 xv = xr[nt * 4];
                float2 o;
                o.x = g * (acc[mt][nt][half * 2 + 0] + be) + xv.x;
                o.y = g * (acc[mt][nt][half * 2 + 1] + be) + xv.y;
                orow[nt * 4] = o;
            }
        }
    }
}

// ---------------- launch ----------------
extern "C" void kernel_launch(void* const* d_in, const int* in_sizes, int n_in,
                              void* d_out, int out_size) {
    const float* x = (const float*)d_in[0];
    const float* y = (const float*)d_in[1];
    const float* wq = (const float*)d_in[2];
    const float* bq = (const float*)d_in[3];
    const float* wk = (const float*)d_in[4];
    const float* bk = (const float*)d_in[5];
    const float* wv = (const float*)d_in[6];
    const float* bv = (const float*)d_in[7];
    const float* gamma = (const float*)d_in[8];
    float* out = (float*)d_out;

    static bool configured = false;
    if (!configured) {
        cudaFuncSetAttribute(k_wgemm, cudaFuncAttributeMaxDynamicSharedMemorySize, WG_SMEM);
        cudaFuncSetAttribute(k_main, cudaFuncAttributeMaxDynamicSharedMemorySize, MM_SMEM);
        configured = true;
    }

    k_zero<<<(B_ * C_ + 255) / 256, 256>>>();
    k_cvtx<<<dim3(HW_ / 64, C_ / 64, B_), 256>>>(x);        // xt fp16 + xsum (atomics)
    k_wvt<<<dim3(C_ / 64, C_ / 64), 256>>>(wv);             // wv^T hi/lo
    k_qvsk<<<dim3(C_ / 64, B_), 256>>>(wq, bq, wk, bk, y);
    k_softmax<<<dim3(C_ / 8, B_), 256>>>(bv);               // attn hi/lo + beff
    k_wgemm<<<dim3(C_ / 128, C_ / 128, B_), 256, WG_SMEM>>>();
    k_main<<<dim3(HW_ / 128, C_ / 128, B_), 256, MM_SMEM>>>(x, out, gamma);
}

// round 7
// speedup vs baseline: 4.1442x; 1.2878x over previous
#include <cuda_runtime.h>
#include <cuda_fp16.h>
#include <cstdint>

#define B_  16
#define C_  512
#define HW_ 4096

// ---------------- scratch (__device__ globals: allocation-free) ----------------
__device__ float g_xsum[B_ * C_];
__device__ float g_qv[B_ * C_];
__device__ float g_sk[B_ * C_];
__device__ float g_beff[B_ * C_];
__device__ __half g_ahi[(size_t)B_ * C_ * C_];   // attn hi  [b][c][d]
__device__ __half g_alo[(size_t)B_ * C_ * C_];   // attn lo
__device__ __half g_wvhi[C_ * C_];               // wv^T hi  [c][o]
__device__ __half g_wvlo[C_ * C_];               // wv^T lo
__device__ __half g_whi[(size_t)B_ * C_ * C_];   // W_eff fp16 [b][m][k]
__device__ __half g_xt[(size_t)B_ * HW_ * C_];   // x^T fp16 [b][n][k]  (67 MB)

// ---------------- helpers ----------------
__device__ __forceinline__ uint32_t smem_u32(const void* p) {
    uint32_t a;
    asm("{ .reg .u64 t; cvta.to.shared.u64 t, %1; cvt.u32.u64 %0, t; }" : "=r"(a) : "l"(p));
    return a;
}
__device__ __forceinline__ void cp_async16(uint32_t dst, const void* src) {
    asm volatile("cp.async.cg.shared.global [%0], [%1], 16;" :: "r"(dst), "l"(src) : "memory");
}
__device__ __forceinline__ void cp_commit() {
    asm volatile("cp.async.commit_group;" ::: "memory");
}
template <int N>
__device__ __forceinline__ void cp_wait() {
    asm volatile("cp.async.wait_group %0;" :: "n"(N) : "memory");
}
__device__ __forceinline__ uint32_t sw64(uint32_t off) { return off ^ ((off >> 3) & 0x30); }

__device__ __forceinline__ void ldsm_x4(uint32_t* r, uint32_t addr) {
    asm volatile("ldmatrix.sync.aligned.m8n8.x4.shared.b16 {%0,%1,%2,%3}, [%4];"
                 : "=r"(r[0]), "=r"(r[1]), "=r"(r[2]), "=r"(r[3]) : "r"(addr));
}
__device__ __forceinline__ void mma16816(float* c, const uint32_t* a, const uint32_t* b) {
    asm volatile(
        "mma.sync.aligned.m16n8k16.row.col.f32.f16.f16.f32 "
        "{%0,%1,%2,%3}, {%4,%5,%6,%7}, {%8,%9}, {%0,%1,%2,%3};"
        : "+f"(c[0]), "+f"(c[1]), "+f"(c[2]), "+f"(c[3])
        : "r"(a[0]), "r"(a[1]), "r"(a[2]), "r"(a[3]), "r"(b[0]), "r"(b[1]));
}

__device__ __forceinline__ float warpSum(float v) {
#pragma unroll
    for (int o = 16; o > 0; o >>= 1) v += __shfl_xor_sync(0xffffffffu, v, o);
    return v;
}
__device__ __forceinline__ float warpMax(float v) {
#pragma unroll
    for (int o = 16; o > 0; o >>= 1) v = fmaxf(v, __shfl_xor_sync(0xffffffffu, v, o));
    return v;
}

// ---------------- kernel 0: zero xsum ----------------
__global__ void k_zero() {
    int t = blockIdx.x * 256 + threadIdx.x;
    if (t < B_ * C_) g_xsum[t] = 0.f;
}

// ---------------- kernel 1: transpose+convert x -> g_xt fp16 [b][n][k], fused xsum ----------------
__global__ void k_cvtx(const float* __restrict__ x) {
    __shared__ float tile[64][65];
    int b = blockIdx.z;
    int n0 = blockIdx.x * 64;
    int k0 = blockIdx.y * 64;
    int t = threadIdx.x;
    int tr = t >> 4, tc = t & 15;

    const float* src = x + ((size_t)b * C_ + k0) * HW_ + n0;
    float psum[4];
#pragma unroll
    for (int i = 0; i < 4; i++) {
        int r = tr + i * 16;  // local k
        float4 v = *(const float4*)(src + (size_t)r * HW_ + tc * 4);
        tile[r][tc * 4 + 0] = v.x;
        tile[r][tc * 4 + 1] = v.y;
        tile[r][tc * 4 + 2] = v.z;
        tile[r][tc * 4 + 3] = v.w;
        psum[i] = (v.x + v.y) + (v.z + v.w);
    }
#pragma unroll
    for (int i = 0; i < 4; i++) {
        float s = psum[i];
#pragma unroll
        for (int o = 8; o > 0; o >>= 1) s += __shfl_xor_sync(0xffffffffu, s, o);
        if (tc == 0) atomicAdd(&g_xsum[b * C_ + k0 + tr + i * 16], s);
    }
    __syncthreads();
#pragma unroll
    for (int i = 0; i < 4; i++) {
        int n = tr + i * 16;  // local n
        size_t base = ((size_t)(b * HW_ + n0 + n)) * C_ + k0 + tc * 4;
        float v0 = tile[tc * 4 + 0][n];
        float v1 = tile[tc * 4 + 1][n];
        float v2 = tile[tc * 4 + 2][n];
        float v3 = tile[tc * 4 + 3][n];
        *(__half2*)&g_xt[base]     = __floats2half2_rn(v0, v1);
        *(__half2*)&g_xt[base + 2] = __floats2half2_rn(v2, v3);
    }
}

// ---------------- kernel 2: wv^T -> fp16 hi/lo [c][o] ----------------
__global__ void k_wvt(const float* __restrict__ wv) {
    __shared__ float tile[64][65];
    int o0 = blockIdx.y * 64;
    int c0 = blockIdx.x * 64;
    int t = threadIdx.x;
    int tr = t >> 4, tc = t & 15;

    const float* src = wv + (size_t)(o0)*C_ + c0;
#pragma unroll
    for (int i = 0; i < 4; i++) {
        int r = tr + i * 16;
        float4 v = *(const float4*)(src + (size_t)r * C_ + tc * 4);
        tile[r][tc * 4 + 0] = v.x;
        tile[r][tc * 4 + 1] = v.y;
        tile[r][tc * 4 + 2] = v.z;
        tile[r][tc * 4 + 3] = v.w;
    }
    __syncthreads();
#pragma unroll
    for (int i = 0; i < 4; i++) {
        int c = tr + i * 16;
        size_t base = (size_t)(c0 + c) * C_ + o0 + tc * 4;
#pragma unroll
        for (int j = 0; j < 4; j += 2) {
            float va = tile[tc * 4 + j][c];
            float vb = tile[tc * 4 + j + 1][c];
            __half2 h = __floats2half2_rn(va, vb);
            __half2 l = __floats2half2_rn(va - __low2float(h), vb - __high2float(h));
            *(__half2*)&g_wvhi[base + j] = h;
            *(__half2*)&g_wvlo[base + j] = l;
        }
    }
}

// ---------------- kernel 3: qv/sk — 1 warp per output ----------------
// grid (C/8, B), 256 threads = 8 warps = 8 outputs (each warp does q AND k dots)
__global__ void k_qvsk(const float* __restrict__ wq, const float* __restrict__ bq,
                       const float* __restrict__ wk, const float* __restrict__ bk,
                       const float* __restrict__ y) {
    int b = blockIdx.y;
    __shared__ float ys[C_], xs[C_];
    for (int i = threadIdx.x; i < C_; i += 256) {
        ys[i] = y[b * C_ + i];
        xs[i] = g_xsum[b * C_ + i];
    }
    __syncthreads();

    int w = threadIdx.x >> 5, lane = threadIdx.x & 31;
    int o = blockIdx.x * 8 + w;
    const float4* wq4 = (const float4*)(wq + (size_t)o * C_);
    const float4* wk4 = (const float4*)(wk + (size_t)o * C_);
    float aq = 0.f, ak = 0.f;
#pragma unroll
    for (int i = 0; i < 4; i++) {
        int c = lane + 32 * i;          // float4 index: covers 512 floats
        float4 a = wq4[c], k4 = wk4[c];
        const float* yp = &ys[4 * c];
        const float* xp = &xs[4 * c];
        aq += a.x * yp[0] + a.y * yp[1] + a.z * yp[2] + a.w * yp[3];
        ak += k4.x * xp[0] + k4.y * xp[1] + k4.z * xp[2] + k4.w * xp[3];
    }
    aq = warpSum(aq);
    ak = warpSum(ak);
    if (lane == 0) {
        g_qv[b * C_ + o] = aq + bq[o];
        g_sk[b * C_ + o] = ak + (float)HW_ * bk[o];
    }
}

// ---------------- kernel 4: softmax -> attn fp16 hi/lo + beff (1 warp/row) ----------------
__global__ void k_softmax(const float* __restrict__ bv) {
    int b = blockIdx.y;
    int w = threadIdx.x >> 5, lane = threadIdx.x & 31;
    int c = blockIdx.x * 8 + w;
    __shared__ float sks[C_], bvs[C_];
    for (int i = threadIdx.x; i < C_; i += 256) {
        sks[i] = g_sk[b * C_ + i];
        bvs[i] = bv[i];
    }
    __syncthreads();

    float q = g_qv[b * C_ + c];
    float e[16];
    float m = -3.4e38f;
#pragma unroll
    for (int i = 0; i < 16; i++) {
        e[i] = q * sks[lane + 32 * i];
        m = fmaxf(m, e[i]);
    }
    m = warpMax(m);
    float s = 0.f;
#pragma unroll
    for (int i = 0; i < 16; i++) {
        e[i] = __expf(e[i] - m);
        s += e[i];
    }
    s = warpSum(s);
    float inv = 1.f / s;
    float bacc = 0.f;
    size_t base = ((size_t)(b * C_ + c)) * C_;
#pragma unroll
    for (int i = 0; i < 16; i++) {
        float a = e[i] * inv;
        __half h = __float2half(a);
        g_ahi[base + lane + 32 * i] = h;
        g_alo[base + lane + 32 * i] = __float2half(a - __half2float(h));
        bacc += a * bvs[lane + 32 * i];
    }
    bacc = warpSum(bacc);
    if (lane == 0) g_beff[b * C_ + c] = bacc;
}

// ---------------- kernel 5: W_eff = attn @ wv^T (fp16 3-pass, 3-stage pipeline) ----------------
// Accurate fp32 accumulation (hh+hl+lh), single fp16 rounding on output.
#define WG_ARR 8192
#define WG_STAGE (4 * WG_ARR)       // 32 KB
#define WG_SMEM (3 * WG_STAGE)      // 96 KB

__global__ __launch_bounds__(256, 1) void k_wgemm() {
    extern __shared__ char smem[];
    uint32_t sb = smem_u32(smem);
    int t = threadIdx.x;
    int wid = t >> 5, lane = t & 31;
    int wm = wid & 3, wn = wid >> 2;
    int b = blockIdx.z;
    int tm = blockIdx.y * 128;
    int tn = blockIdx.x * 128;

    const __half* srcAh = g_ahi + ((size_t)b * C_ + tm) * C_;
    const __half* srcAl = g_alo + ((size_t)b * C_ + tm) * C_;
    const __half* srcBh = g_wvhi + (size_t)tn * C_;
    const __half* srcBl = g_wvlo + (size_t)tn * C_;

    int lrow = t >> 2;
    int lc = t & 3;

    auto load_stage = [&](int kt, int st) {
        uint32_t base = sb + st * WG_STAGE;
#pragma unroll
        for (int i = 0; i < 2; i++) {
            int row = lrow + i * 64;
            uint32_t soff = sw64((uint32_t)(row * 64 + lc * 16));
            size_t goff = (size_t)row * C_ + kt * 32 + lc * 8;
            cp_async16(base + soff, srcAh + goff);
            cp_async16(base + WG_ARR + soff, srcAl + goff);
            cp_async16(base + 2 * WG_ARR + soff, srcBh + goff);
            cp_async16(base + 3 * WG_ARR + soff, srcBl + goff);
        }
        cp_commit();
    };

    float acc[2][8][4];
#pragma unroll
    for (int mt = 0; mt < 2; mt++)
#pragma unroll
        for (int nt = 0; nt < 8; nt++)
#pragma unroll
            for (int q = 0; q < 4; q++) acc[mt][nt][q] = 0.f;

    load_stage(0, 0);
    load_stage(1, 1);

#pragma unroll 1
    for (int kt = 0; kt < 16; kt++) {
        if (kt < 14) cp_wait<1>();
        else cp_wait<0>();
        __syncthreads();
        if (kt + 2 < 16) load_stage(kt + 2, (kt + 2) % 3);

        uint32_t Ah = sb + (kt % 3) * WG_STAGE;
        uint32_t Al = Ah + WG_ARR;
        uint32_t Bh = Ah + 2 * WG_ARR;
        uint32_t Bl = Ah + 3 * WG_ARR;

#pragma unroll
        for (int s = 0; s < 2; s++) {
            uint32_t ah[2][4], al[2][4];
#pragma unroll
            for (int mt = 0; mt < 2; mt++) {
                int row = wm * 32 + mt * 16 + (lane & 15);
                int ch = 2 * s + (lane >> 4);
                uint32_t off = sw64((uint32_t)(row * 64 + ch * 16));
                ldsm_x4(ah[mt], Ah + off);
                ldsm_x4(al[mt], Al + off);
            }
            uint32_t bh[8][2], bl[8][2];
#pragma unroll
            for (int ng = 0; ng < 4; ng++) {
                int row = wn * 64 + ng * 16 + (lane & 7) + ((lane & 16) >> 1);
                int ch = 2 * s + ((lane >> 3) & 1);
                uint32_t off = sw64((uint32_t)(row * 64 + ch * 16));
                uint32_t r4[4];
                ldsm_x4(r4, Bh + off);
                bh[ng * 2 + 0][0] = r4[0]; bh[ng * 2 + 0][1] = r4[1];
                bh[ng * 2 + 1][0] = r4[2]; bh[ng * 2 + 1][1] = r4[3];
                ldsm_x4(r4, Bl + off);
                bl[ng * 2 + 0][0] = r4[0]; bl[ng * 2 + 0][1] = r4[1];
                bl[ng * 2 + 1][0] = r4[2]; bl[ng * 2 + 1][1] = r4[3];
            }
#pragma unroll
            for (int mt = 0; mt < 2; mt++)
#pragma unroll
                for (int nt = 0; nt < 8; nt++) {
                    mma16816(acc[mt][nt], ah[mt], bh[nt]);
                    mma16816(acc[mt][nt], ah[mt], bl[nt]);
                    mma16816(acc[mt][nt], al[mt], bh[nt]);
                }
        }
    }

    int r0 = tm + wm * 32 + (lane >> 2);
    int c0 = tn + wn * 64 + (lane & 3) * 2;
#pragma unroll
    for (int mt = 0; mt < 2; mt++) {
#pragma unroll
        for (int half = 0; half < 2; half++) {
            int row = r0 + mt * 16 + half * 8;
            size_t rbase = ((size_t)(b * C_ + row)) * C_;
#pragma unroll
            for (int nt = 0; nt < 8; nt++) {
                int col = c0 + nt * 8;
                *(__half2*)&g_whi[rbase + col] =
                    __floats2half2_rn(acc[mt][nt][half * 2 + 0], acc[mt][nt][half * 2 + 1]);
            }
        }
    }
}

// ---------------- kernel 6: main GEMM, single fp16 pass, 3-stage pipeline ----------------
#define MM_ARR 8192
#define MM_STAGE (2 * MM_ARR)       // 16 KB (Ah, Bh)
#define MM_SMEM (3 * MM_STAGE)      // 48 KB

__global__ __launch_bounds__(256, 2) void k_main(
    const float* __restrict__ x, float* __restrict__ out,
    const float* __restrict__ gamma) {
    extern __shared__ char smem[];
    uint32_t sb = smem_u32(smem);
    int t = threadIdx.x;
    int wid = t >> 5, lane = t & 31;
    int wm = wid & 3, wn = wid >> 2;
    int b = blockIdx.z;
    int tm = blockIdx.y * 128;
    int tn = blockIdx.x * 128;

    const __half* srcAh = g_whi + ((size_t)b * C_ + tm) * C_;
    const __half* srcBh = g_xt + ((size_t)b * HW_ + tn) * C_;

    int lrow = t >> 2;
    int lc = t & 3;

    auto load_stage = [&](int kt, int st) {
        uint32_t base = sb + st * MM_STAGE;
#pragma unroll
        for (int i = 0; i < 2; i++) {
            int row = lrow + i * 64;
            uint32_t soff = sw64((uint32_t)(row * 64 + lc * 16));
            size_t goff = (size_t)row * C_ + kt * 32 + lc * 8;
            cp_async16(base + soff, srcAh + goff);
            cp_async16(base + MM_ARR + soff, srcBh + goff);
        }
        cp_commit();
    };

    float acc[2][8][4];
#pragma unroll
    for (int mt = 0; mt < 2; mt++)
#pragma unroll
        for (int nt = 0; nt < 8; nt++)
#pragma unroll
            for (int q = 0; q < 4; q++) acc[mt][nt][q] = 0.f;

    load_stage(0, 0);
    load_stage(1, 1);

#pragma unroll 1
    for (int kt = 0; kt < 16; kt++) {
        if (kt < 14) cp_wait<1>();
        else cp_wait<0>();
        __syncthreads();
        if (kt + 2 < 16) load_stage(kt + 2, (kt + 2) % 3);

        uint32_t Ah = sb + (kt % 3) * MM_STAGE;
        uint32_t Bh = Ah + MM_ARR;

#pragma unroll
        for (int s = 0; s < 2; s++) {
            uint32_t ah[2][4];
#pragma unroll
            for (int mt = 0; mt < 2; mt++) {
                int row = wm * 32 + mt * 16 + (lane & 15);
                int ch = 2 * s + (lane >> 4);
                uint32_t off = sw64((uint32_t)(row * 64 + ch * 16));
                ldsm_x4(ah[mt], Ah + off);
            }
            uint32_t bh[8][2];
#pragma unroll
            for (int ng = 0; ng < 4; ng++) {
                int row = wn * 64 + ng * 16 + (lane & 7) + ((lane & 16) >> 1);
                int ch = 2 * s + ((lane >> 3) & 1);
                uint32_t off = sw64((uint32_t)(row * 64 + ch * 16));
                uint32_t r4[4];
                ldsm_x4(r4, Bh + off);
                bh[ng * 2 + 0][0] = r4[0]; bh[ng * 2 + 0][1] = r4[1];
                bh[ng * 2 + 1][0] = r4[2]; bh[ng * 2 + 1][1] = r4[3];
            }
#pragma unroll
            for (int mt = 0; mt < 2; mt++)
#pragma unroll
                for (int nt = 0; nt < 8; nt++)
                    mma16816(acc[mt][nt], ah[mt], bh[nt]);
        }
    }

    // epilogue: out = gamma*(acc + beff) + x
    float g = *gamma;
    int r0 = tm + wm * 32 + (lane >> 2);
    int c0 = tn + wn * 64 + (lane & 3) * 2;
#pragma unroll
    for (int mt = 0; mt < 2; mt++) {
#pragma unroll
        for (int half = 0; half < 2; half++) {
            int row = r0 + mt * 16 + half * 8;
            float be = g_beff[b * C_ + row];
            const float2* xr = (const float2*)(x + ((size_t)b * C_ + row) * HW_ + c0);
            float2* orow = (float2*)(out + ((size_t)b * C_ + row) * HW_ + c0);
#pragma unroll
            for (int nt = 0; nt < 8; nt++) {
                float2 xv = xr[nt * 4];
                float2 o;
                o.x = g * (acc[mt][nt][half * 2 + 0] + be) + xv.x;
                o.y = g * (acc[mt][nt][half * 2 + 1] + be) + xv.y;
                orow[nt * 4] = o;
            }
        }
    }
}

// ---------------- launch ----------------
extern "C" void kernel_launch(void* const* d_in, const int* in_sizes, int n_in,
                              void* d_out, int out_size) {
    const float* x = (const float*)d_in[0];
    const float* y = (const float*)d_in[1];
    const float* wq = (const float*)d_in[2];
    const float* bq = (const float*)d_in[3];
    const float* wk = (const float*)d_in[4];
    const float* bk = (const float*)d_in[5];
    const float* wv = (const float*)d_in[6];
    const float* bv = (const float*)d_in[7];
    const float* gamma = (const float*)d_in[8];
    float* out = (float*)d_out;

    static bool configured = false;
    if (!configured) {
        cudaFuncSetAttribute(k_wgemm, cudaFuncAttributeMaxDynamicSharedMemorySize, WG_SMEM);
        cudaFuncSetAttribute(k_main, cudaFuncAttributeMaxDynamicSharedMemorySize, MM_SMEM);
        configured = true;
    }

    k_zero<<<(B_ * C_ + 255) / 256, 256>>>();
    k_cvtx<<<dim3(HW_ / 64, C_ / 64, B_), 256>>>(x);        // xt fp16 + xsum (atomics)
    k_wvt<<<dim3(C_ / 64, C_ / 64), 256>>>(wv);             // wv^T hi/lo
    k_qvsk<<<dim3(C_ / 8, B_), 256>>>(wq, bq, wk, bk, y);
    k_softmax<<<dim3(C_ / 8, B_), 256>>>(bv);               // attn hi/lo + beff
    k_wgemm<<<dim3(C_ / 128, C_ / 128, B_), 256, WG_SMEM>>>();
    k_main<<<dim3(HW_ / 128, C_ / 128, B_), 256, MM_SMEM>>>(x, out, gamma);
}

// round 8
// speedup vs baseline: 4.4364x; 1.0705x over previous
#include <cuda_runtime.h>
#include <cuda_fp16.h>
#include <cstdint>

#define B_  16
#define C_  512
#define HW_ 4096

// ---------------- scratch (__device__ globals: allocation-free) ----------------
__device__ float g_xsum[B_ * C_];
__device__ float g_qv[B_ * C_];
__device__ float g_sk[B_ * C_];
__device__ float g_beff[B_ * C_];
__device__ __half g_ahi[(size_t)B_ * C_ * C_];   // attn fp16 [b][c][d]
__device__ __half g_wvhi[C_ * C_];               // wv^T fp16 [c][o]
__device__ __half g_whi[(size_t)B_ * C_ * C_];   // W_eff fp16 [b][m][k]
__device__ __half g_xt[(size_t)B_ * HW_ * C_];   // x^T fp16 [b][n][k]  (67 MB)

// ---------------- helpers ----------------
__device__ __forceinline__ uint32_t smem_u32(const void* p) {
    uint32_t a;
    asm("{ .reg .u64 t; cvta.to.shared.u64 t, %1; cvt.u32.u64 %0, t; }" : "=r"(a) : "l"(p));
    return a;
}
__device__ __forceinline__ void cp_async16(uint32_t dst, const void* src) {
    asm volatile("cp.async.cg.shared.global [%0], [%1], 16;" :: "r"(dst), "l"(src) : "memory");
}
__device__ __forceinline__ void cp_commit() {
    asm volatile("cp.async.commit_group;" ::: "memory");
}
template <int N>
__device__ __forceinline__ void cp_wait() {
    asm volatile("cp.async.wait_group %0;" :: "n"(N) : "memory");
}
__device__ __forceinline__ uint32_t sw64(uint32_t off) { return off ^ ((off >> 3) & 0x30); }

__device__ __forceinline__ void ldsm_x4(uint32_t* r, uint32_t addr) {
    asm volatile("ldmatrix.sync.aligned.m8n8.x4.shared.b16 {%0,%1,%2,%3}, [%4];"
                 : "=r"(r[0]), "=r"(r[1]), "=r"(r[2]), "=r"(r[3]) : "r"(addr));
}
__device__ __forceinline__ void mma16816(float* c, const uint32_t* a, const uint32_t* b) {
    asm volatile(
        "mma.sync.aligned.m16n8k16.row.col.f32.f16.f16.f32 "
        "{%0,%1,%2,%3}, {%4,%5,%6,%7}, {%8,%9}, {%0,%1,%2,%3};"
        : "+f"(c[0]), "+f"(c[1]), "+f"(c[2]), "+f"(c[3])
        : "r"(a[0]), "r"(a[1]), "r"(a[2]), "r"(a[3]), "r"(b[0]), "r"(b[1]));
}

__device__ __forceinline__ float warpSum(float v) {
#pragma unroll
    for (int o = 16; o > 0; o >>= 1) v += __shfl_xor_sync(0xffffffffu, v, o);
    return v;
}
__device__ __forceinline__ float warpMax(float v) {
#pragma unroll
    for (int o = 16; o > 0; o >>= 1) v = fmaxf(v, __shfl_xor_sync(0xffffffffu, v, o));
    return v;
}

// ---------------- kernel A: xsum[b,c] = sum_n x[b,c,n] ----------------
__global__ void k_xsum(const float* __restrict__ x) {
    int row = blockIdx.x;
    const float4* p = (const float4*)(x + (size_t)row * HW_);
    float s = 0.f;
#pragma unroll 4
    for (int i = threadIdx.x; i < HW_ / 4; i += 256) {
        float4 v = p[i];
        s += (v.x + v.y) + (v.z + v.w);
    }
    __shared__ float red[8];
    s = warpSum(s);
    if ((threadIdx.x & 31) == 0) red[threadIdx.x >> 5] = s;
    __syncthreads();
    if (threadIdx.x == 0) {
        float t = 0.f;
#pragma unroll
        for (int i = 0; i < 8; i++) t += red[i];
        g_xsum[row] = t;
    }
}

// ---------------- kernel B: transpose+convert x -> g_xt fp16 [b][n][k] ----------------
__global__ void k_cvtx(const float* __restrict__ x) {
    __shared__ float tile[64][65];
    int b = blockIdx.z;
    int n0 = blockIdx.x * 64;
    int k0 = blockIdx.y * 64;
    int t = threadIdx.x;
    int tr = t >> 4, tc = t & 15;

    const float* src = x + ((size_t)b * C_ + k0) * HW_ + n0;
#pragma unroll
    for (int i = 0; i < 4; i++) {
        int r = tr + i * 16;  // local k
        float4 v = *(const float4*)(src + (size_t)r * HW_ + tc * 4);
        tile[r][tc * 4 + 0] = v.x;
        tile[r][tc * 4 + 1] = v.y;
        tile[r][tc * 4 + 2] = v.z;
        tile[r][tc * 4 + 3] = v.w;
    }
    __syncthreads();
#pragma unroll
    for (int i = 0; i < 4; i++) {
        int n = tr + i * 16;  // local n
        size_t base = ((size_t)(b * HW_ + n0 + n)) * C_ + k0 + tc * 4;
        float v0 = tile[tc * 4 + 0][n];
        float v1 = tile[tc * 4 + 1][n];
        float v2 = tile[tc * 4 + 2][n];
        float v3 = tile[tc * 4 + 3][n];
        *(__half2*)&g_xt[base]     = __floats2half2_rn(v0, v1);
        *(__half2*)&g_xt[base + 2] = __floats2half2_rn(v2, v3);
    }
}

// ---------------- kernel C: wv^T -> fp16 [c][o] ----------------
__global__ void k_wvt(const float* __restrict__ wv) {
    __shared__ float tile[64][65];
    int o0 = blockIdx.y * 64;
    int c0 = blockIdx.x * 64;
    int t = threadIdx.x;
    int tr = t >> 4, tc = t & 15;

    const float* src = wv + (size_t)(o0)*C_ + c0;
#pragma unroll
    for (int i = 0; i < 4; i++) {
        int r = tr + i * 16;
        float4 v = *(const float4*)(src + (size_t)r * C_ + tc * 4);
        tile[r][tc * 4 + 0] = v.x;
        tile[r][tc * 4 + 1] = v.y;
        tile[r][tc * 4 + 2] = v.z;
        tile[r][tc * 4 + 3] = v.w;
    }
    __syncthreads();
#pragma unroll
    for (int i = 0; i < 4; i++) {
        int c = tr + i * 16;
        size_t base = (size_t)(c0 + c) * C_ + o0 + tc * 4;
        *(__half2*)&g_wvhi[base] = __floats2half2_rn(tile[tc * 4 + 0][c], tile[tc * 4 + 1][c]);
        *(__half2*)&g_wvhi[base + 2] = __floats2half2_rn(tile[tc * 4 + 2][c], tile[tc * 4 + 3][c]);
    }
}

// ---------------- kernel D: qv/sk — 1 warp per output ----------------
__global__ void k_qvsk(const float* __restrict__ wq, const float* __restrict__ bq,
                       const float* __restrict__ wk, const float* __restrict__ bk,
                       const float* __restrict__ y) {
    int b = blockIdx.y;
    __shared__ float ys[C_], xs[C_];
    for (int i = threadIdx.x; i < C_; i += 256) {
        ys[i] = y[b * C_ + i];
        xs[i] = g_xsum[b * C_ + i];
    }
    __syncthreads();

    int w = threadIdx.x >> 5, lane = threadIdx.x & 31;
    int o = blockIdx.x * 8 + w;
    const float4* wq4 = (const float4*)(wq + (size_t)o * C_);
    const float4* wk4 = (const float4*)(wk + (size_t)o * C_);
    float aq = 0.f, ak = 0.f;
#pragma unroll
    for (int i = 0; i < 4; i++) {
        int c = lane + 32 * i;
        float4 a = wq4[c], k4 = wk4[c];
        const float* yp = &ys[4 * c];
        const float* xp = &xs[4 * c];
        aq += a.x * yp[0] + a.y * yp[1] + a.z * yp[2] + a.w * yp[3];
        ak += k4.x * xp[0] + k4.y * xp[1] + k4.z * xp[2] + k4.w * xp[3];
    }
    aq = warpSum(aq);
    ak = warpSum(ak);
    if (lane == 0) {
        g_qv[b * C_ + o] = aq + bq[o];
        g_sk[b * C_ + o] = ak + (float)HW_ * bk[o];
    }
}

// ---------------- kernel E: softmax -> attn fp16 + beff (1 warp/row) ----------------
__global__ void k_softmax(const float* __restrict__ bv) {
    int b = blockIdx.y;
    int w = threadIdx.x >> 5, lane = threadIdx.x & 31;
    int c = blockIdx.x * 8 + w;
    __shared__ float sks[C_], bvs[C_];
    for (int i = threadIdx.x; i < C_; i += 256) {
        sks[i] = g_sk[b * C_ + i];
        bvs[i] = bv[i];
    }
    __syncthreads();

    float q = g_qv[b * C_ + c];
    float e[16];
    float m = -3.4e38f;
#pragma unroll
    for (int i = 0; i < 16; i++) {
        e[i] = q * sks[lane + 32 * i];
        m = fmaxf(m, e[i]);
    }
    m = warpMax(m);
    float s = 0.f;
#pragma unroll
    for (int i = 0; i < 16; i++) {
        e[i] = __expf(e[i] - m);
        s += e[i];
    }
    s = warpSum(s);
    float inv = 1.f / s;
    float bacc = 0.f;
    size_t base = ((size_t)(b * C_ + c)) * C_;
#pragma unroll
    for (int i = 0; i < 16; i++) {
        float a = e[i] * inv;
        g_ahi[base + lane + 32 * i] = __float2half(a);
        bacc += a * bvs[lane + 32 * i];
    }
    bacc = warpSum(bacc);
    if (lane == 0) g_beff[b * C_ + c] = bacc;
}

// ---------------- kernel F: W_eff = attn @ wv^T (single fp16 pass, 3-stage) ----------------
#define WG_ARR 8192
#define WG_STAGE (2 * WG_ARR)       // 16 KB
#define WG_SMEM (3 * WG_STAGE)      // 48 KB

__global__ __launch_bounds__(256, 2) void k_wgemm() {
    extern __shared__ char smem[];
    uint32_t sb = smem_u32(smem);
    int t = threadIdx.x;
    int wid = t >> 5, lane = t & 31;
    int wm = wid & 3, wn = wid >> 2;
    int b = blockIdx.z;
    int tm = blockIdx.y * 128;
    int tn = blockIdx.x * 128;

    const __half* srcAh = g_ahi + ((size_t)b * C_ + tm) * C_;
    const __half* srcBh = g_wvhi + (size_t)tn * C_;

    int lrow = t >> 2;
    int lc = t & 3;

    auto load_stage = [&](int kt, int st) {
        uint32_t base = sb + st * WG_STAGE;
#pragma unroll
        for (int i = 0; i < 2; i++) {
            int row = lrow + i * 64;
            uint32_t soff = sw64((uint32_t)(row * 64 + lc * 16));
            size_t goff = (size_t)row * C_ + kt * 32 + lc * 8;
            cp_async16(base + soff, srcAh + goff);
            cp_async16(base + WG_ARR + soff, srcBh + goff);
        }
        cp_commit();
    };

    float acc[2][8][4];
#pragma unroll
    for (int mt = 0; mt < 2; mt++)
#pragma unroll
        for (int nt = 0; nt < 8; nt++)
#pragma unroll
            for (int q = 0; q < 4; q++) acc[mt][nt][q] = 0.f;

    load_stage(0, 0);
    load_stage(1, 1);

#pragma unroll 1
    for (int kt = 0; kt < 16; kt++) {
        if (kt < 14) cp_wait<1>();
        else cp_wait<0>();
        __syncthreads();
        if (kt + 2 < 16) load_stage(kt + 2, (kt + 2) % 3);

        uint32_t Ah = sb + (kt % 3) * WG_STAGE;
        uint32_t Bh = Ah + WG_ARR;

#pragma unroll
        for (int s = 0; s < 2; s++) {
            uint32_t ah[2][4];
#pragma unroll
            for (int mt = 0; mt < 2; mt++) {
                int row = wm * 32 + mt * 16 + (lane & 15);
                int ch = 2 * s + (lane >> 4);
                uint32_t off = sw64((uint32_t)(row * 64 + ch * 16));
                ldsm_x4(ah[mt], Ah + off);
            }
            uint32_t bh[8][2];
#pragma unroll
            for (int ng = 0; ng < 4; ng++) {
                int row = wn * 64 + ng * 16 + (lane & 7) + ((lane & 16) >> 1);
                int ch = 2 * s + ((lane >> 3) & 1);
                uint32_t off = sw64((uint32_t)(row * 64 + ch * 16));
                uint32_t r4[4];
                ldsm_x4(r4, Bh + off);
                bh[ng * 2 + 0][0] = r4[0]; bh[ng * 2 + 0][1] = r4[1];
                bh[ng * 2 + 1][0] = r4[2]; bh[ng * 2 + 1][1] = r4[3];
            }
#pragma unroll
            for (int mt = 0; mt < 2; mt++)
#pragma unroll
                for (int nt = 0; nt < 8; nt++)
                    mma16816(acc[mt][nt], ah[mt], bh[nt]);
        }
    }

    int r0 = tm + wm * 32 + (lane >> 2);
    int c0 = tn + wn * 64 + (lane & 3) * 2;
#pragma unroll
    for (int mt = 0; mt < 2; mt++) {
#pragma unroll
        for (int half = 0; half < 2; half++) {
            int row = r0 + mt * 16 + half * 8;
            size_t rbase = ((size_t)(b * C_ + row)) * C_;
#pragma unroll
            for (int nt = 0; nt < 8; nt++) {
                int col = c0 + nt * 8;
                *(__half2*)&g_whi[rbase + col] =
                    __floats2half2_rn(acc[mt][nt][half * 2 + 0], acc[mt][nt][half * 2 + 1]);
            }
        }
    }
}

// ---------------- kernel G: main GEMM, single fp16 pass, 3-stage pipeline ----------------
#define MM_ARR 8192
#define MM_STAGE (2 * MM_ARR)       // 16 KB (Ah, Bh)
#define MM_SMEM (3 * MM_STAGE)      // 48 KB

__global__ __launch_bounds__(256, 2) void k_main(
    const float* __restrict__ x, float* __restrict__ out,
    const float* __restrict__ gamma) {
    extern __shared__ char smem[];
    uint32_t sb = smem_u32(smem);
    int t = threadIdx.x;
    int wid = t >> 5, lane = t & 31;
    int wm = wid & 3, wn = wid >> 2;
    int b = blockIdx.z;
    int tm = blockIdx.y * 128;
    int tn = blockIdx.x * 128;

    const __half* srcAh = g_whi + ((size_t)b * C_ + tm) * C_;
    const __half* srcBh = g_xt + ((size_t)b * HW_ + tn) * C_;

    int lrow = t >> 2;
    int lc = t & 3;

    auto load_stage = [&](int kt, int st) {
        uint32_t base = sb + st * MM_STAGE;
#pragma unroll
        for (int i = 0; i < 2; i++) {
            int row = lrow + i * 64;
            uint32_t soff = sw64((uint32_t)(row * 64 + lc * 16));
            size_t goff = (size_t)row * C_ + kt * 32 + lc * 8;
            cp_async16(base + soff, srcAh + goff);
            cp_async16(base + MM_ARR + soff, srcBh + goff);
        }
        cp_commit();
    };

    float acc[2][8][4];
#pragma unroll
    for (int mt = 0; mt < 2; mt++)
#pragma unroll
        for (int nt = 0; nt < 8; nt++)
#pragma unroll
            for (int q = 0; q < 4; q++) acc[mt][nt][q] = 0.f;

    load_stage(0, 0);
    load_stage(1, 1);

#pragma unroll 1
    for (int kt = 0; kt < 16; kt++) {
        if (kt < 14) cp_wait<1>();
        else cp_wait<0>();
        __syncthreads();
        if (kt + 2 < 16) load_stage(kt + 2, (kt + 2) % 3);

        uint32_t Ah = sb + (kt % 3) * MM_STAGE;
        uint32_t Bh = Ah + MM_ARR;

#pragma unroll
        for (int s = 0; s < 2; s++) {
            uint32_t ah[2][4];
#pragma unroll
            for (int mt = 0; mt < 2; mt++) {
                int row = wm * 32 + mt * 16 + (lane & 15);
                int ch = 2 * s + (lane >> 4);
                uint32_t off = sw64((uint32_t)(row * 64 + ch * 16));
                ldsm_x4(ah[mt], Ah + off);
            }
            uint32_t bh[8][2];
#pragma unroll
            for (int ng = 0; ng < 4; ng++) {
                int row = wn * 64 + ng * 16 + (lane & 7) + ((lane & 16) >> 1);
                int ch = 2 * s + ((lane >> 3) & 1);
                uint32_t off = sw64((uint32_t)(row * 64 + ch * 16));
                uint32_t r4[4];
                ldsm_x4(r4, Bh + off);
                bh[ng * 2 + 0][0] = r4[0]; bh[ng * 2 + 0][1] = r4[1];
                bh[ng * 2 + 1][0] = r4[2]; bh[ng * 2 + 1][1] = r4[3];
            }
#pragma unroll
            for (int mt = 0; mt < 2; mt++)
#pragma unroll
                for (int nt = 0; nt < 8; nt++)
                    mma16816(acc[mt][nt], ah[mt], bh[nt]);
        }
    }

    // epilogue: out = gamma*(acc + beff) + x
    float g = *gamma;
    int r0 = tm + wm * 32 + (lane >> 2);
    int c0 = tn + wn * 64 + (lane & 3) * 2;
#pragma unroll
    for (int mt = 0; mt < 2; mt++) {
#pragma unroll
        for (int half = 0; half < 2; half++) {
            int row = r0 + mt * 16 + half * 8;
            float be = g_beff[b * C_ + row];
            const float2* xr = (const float2*)(x + ((size_t)b * C_ + row) * HW_ + c0);
            float2* orow = (float2*)(out + ((size_t)b * C_ + row) * HW_ + c0);
#pragma unroll
            for (int nt = 0; nt < 8; nt++) {
                float2 xv = xr[nt * 4];
                float2 o;
                o.x = g * (acc[mt][nt][half * 2 + 0] + be) + xv.x;
                o.y = g * (acc[mt][nt][half * 2 + 1] + be) + xv.y;
                orow[nt * 4] = o;
            }
        }
    }
}

// ---------------- launch: parallel graph via event fork/join ----------------
extern "C" void kernel_launch(void* const* d_in, const int* in_sizes, int n_in,
                              void* d_out, int out_size) {
    const float* x = (const float*)d_in[0];
    const float* y = (const float*)d_in[1];
    const float* wq = (const float*)d_in[2];
    const float* bq = (const float*)d_in[3];
    const float* wk = (const float*)d_in[4];
    const float* bk = (const float*)d_in[5];
    const float* wv = (const float*)d_in[6];
    const float* bv = (const float*)d_in[7];
    const float* gamma = (const float*)d_in[8];
    float* out = (float*)d_out;

    static cudaStream_t s2 = nullptr, s3 = nullptr;
    static cudaEvent_t evRoot = nullptr, evCvt = nullptr, evWvt = nullptr;
    static bool configured = false;
    if (!configured) {
        cudaFuncSetAttribute(k_wgemm, cudaFuncAttributeMaxDynamicSharedMemorySize, WG_SMEM);
        cudaFuncSetAttribute(k_main, cudaFuncAttributeMaxDynamicSharedMemorySize, MM_SMEM);
        cudaStreamCreateWithFlags(&s2, cudaStreamNonBlocking);
        cudaStreamCreateWithFlags(&s3, cudaStreamNonBlocking);
        cudaEventCreateWithFlags(&evRoot, cudaEventDisableTiming);
        cudaEventCreateWithFlags(&evCvt, cudaEventDisableTiming);
        cudaEventCreateWithFlags(&evWvt, cudaEventDisableTiming);
        configured = true;
    }

    // fork
    cudaEventRecord(evRoot, 0);
    cudaStreamWaitEvent(s2, evRoot, 0);
    cudaStreamWaitEvent(s3, evRoot, 0);

    // branch s2: x transpose/convert (feeds only k_main)
    k_cvtx<<<dim3(HW_ / 64, C_ / 64, B_), 256, 0, s2>>>(x);
    cudaEventRecord(evCvt, s2);

    // branch s3: wv transpose/convert (feeds k_wgemm)
    k_wvt<<<dim3(C_ / 64, C_ / 64), 256, 0, s3>>>(wv);
    cudaEventRecord(evWvt, s3);

    // main chain on stream 0
    k_xsum<<<B_ * C_, 256>>>(x);
    k_qvsk<<<dim3(C_ / 8, B_), 256>>>(wq, bq, wk, bk, y);
    k_softmax<<<dim3(C_ / 8, B_), 256>>>(bv);
    cudaStreamWaitEvent(0, evWvt, 0);
    k_wgemm<<<dim3(C_ / 128, C_ / 128, B_), 256, WG_SMEM>>>();
    cudaStreamWaitEvent(0, evCvt, 0);
    k_main<<<dim3(HW_ / 128, C_ / 128, B_), 256, MM_SMEM>>>(x, out, gamma);
}